// round 1
// baseline (speedup 1.0000x reference)
#include <cuda_runtime.h>
#include <cuda_bf16.h>

// Problem constants
#define BB 8
#define TT 1024
#define EE 1024
#define HH 16
#define DD 64
#define MROWS (BB * TT)   // 8192

// Scratch (allocation-free rule: __device__ globals)
__device__ float g_Q[MROWS * EE];
__device__ float g_K[MROWS * EE];
__device__ float g_V[MROWS * EE];
__device__ float g_O[MROWS * EE];

// ---------------------------------------------------------------------------
// SGEMM: Y[M,N] = X[M,K] @ W[N,K]^T + bias[N]
// 128x128 tile, BK=16, 256 threads, 8x8 per thread.
// ---------------------------------------------------------------------------
__global__ __launch_bounds__(256) void sgemm_bias_kernel(
    const float* __restrict__ X, const float* __restrict__ W,
    const float* __restrict__ bias, float* __restrict__ Y,
    int M, int N, int K)
{
    __shared__ float As[16][128];   // [k][m]
    __shared__ float Bs[16][128];   // [k][n]

    const int tid = threadIdx.x;
    const int tx = tid & 15;
    const int ty = tid >> 4;
    const int row0 = blockIdx.y * 128;
    const int col0 = blockIdx.x * 128;

    float acc[8][8];
#pragma unroll
    for (int i = 0; i < 8; i++)
#pragma unroll
        for (int j = 0; j < 8; j++) acc[i][j] = 0.0f;

    for (int k0 = 0; k0 < K; k0 += 16) {
        // Load A tile (128 rows x 16 k) as float4, store transposed [k][m]
#pragma unroll
        for (int l = 0; l < 2; l++) {
            int f = tid + l * 256;          // 0..511 float4 slots
            int r = f >> 2;                 // row in tile
            int c4 = f & 3;                 // float4 col
            float4 v = *(const float4*)(X + (size_t)(row0 + r) * K + k0 + c4 * 4);
            As[c4 * 4 + 0][r] = v.x;
            As[c4 * 4 + 1][r] = v.y;
            As[c4 * 4 + 2][r] = v.z;
            As[c4 * 4 + 3][r] = v.w;
        }
        // Load B tile (W rows are the N dim; K contiguous) store [k][n]
#pragma unroll
        for (int l = 0; l < 2; l++) {
            int f = tid + l * 256;
            int r = f >> 2;
            int c4 = f & 3;
            float4 v = *(const float4*)(W + (size_t)(col0 + r) * K + k0 + c4 * 4);
            Bs[c4 * 4 + 0][r] = v.x;
            Bs[c4 * 4 + 1][r] = v.y;
            Bs[c4 * 4 + 2][r] = v.z;
            Bs[c4 * 4 + 3][r] = v.w;
        }
        __syncthreads();

#pragma unroll
        for (int kk = 0; kk < 16; kk++) {
            float a[8], bb[8];
#pragma unroll
            for (int i = 0; i < 8; i++) a[i] = As[kk][ty * 8 + i];
#pragma unroll
            for (int j = 0; j < 8; j++) bb[j] = Bs[kk][tx * 8 + j];
#pragma unroll
            for (int i = 0; i < 8; i++)
#pragma unroll
                for (int j = 0; j < 8; j++)
                    acc[i][j] = fmaf(a[i], bb[j], acc[i][j]);
        }
        __syncthreads();
    }

#pragma unroll
    for (int i = 0; i < 8; i++) {
        int row = row0 + ty * 8 + i;
#pragma unroll
        for (int j = 0; j < 8; j++) {
            int col = col0 + tx * 8 + j;
            Y[(size_t)row * N + col] = acc[i][j] + bias[col];
        }
    }
}

// ---------------------------------------------------------------------------
// Flash-attention style kernel.
// Grid: (T/64, B*H). Block 256 threads (16x16).
// Each thread owns a 4x4 micro-tile: rows ty*4..+3, cols tx*4..+3.
// ---------------------------------------------------------------------------
__global__ __launch_bounds__(256) void attn_kernel(
    const float* __restrict__ Q, const float* __restrict__ K,
    const float* __restrict__ V, float* __restrict__ O)
{
    __shared__ float Qs[64][64];    // [row][d]
    __shared__ float KVs[64][64];   // K phase: [d][key] ; V phase: [key][d]
    __shared__ float Ps[64][64];    // [row][key]

    const int tid = threadIdx.x;
    const int tx = tid & 15;
    const int ty = tid >> 4;
    const int qt = blockIdx.x;               // query tile
    const int bh = blockIdx.y;               // b*H + h
    const int b = bh >> 4;
    const int h = bh & 15;
    const size_t base = ((size_t)b * TT) * EE + (size_t)h * DD;

    // Load Q tile (64 rows x 64 d)
#pragma unroll
    for (int l = 0; l < 4; l++) {
        int f = tid + l * 256;               // 0..1023 float4 slots
        int r = f >> 4;
        int c4 = f & 15;
        float4 v = *(const float4*)(Q + base + (size_t)(qt * 64 + r) * EE + c4 * 4);
        *(float4*)&Qs[r][c4 * 4] = v;
    }

    float m_i[4], l_i[4], o[4][4];
#pragma unroll
    for (int i = 0; i < 4; i++) {
        m_i[i] = -1e30f;
        l_i[i] = 0.0f;
#pragma unroll
        for (int j = 0; j < 4; j++) o[i][j] = 0.0f;
    }

    const float scale = 0.125f;  // 1/sqrt(64)

    for (int kt = 0; kt < 16; kt++) {
        __syncthreads();  // previous-iteration reads of KVs/Ps done

        // Load K tile transposed: KVs[d][key]
#pragma unroll
        for (int l = 0; l < 4; l++) {
            int f = tid + l * 256;
            int r = f >> 4;                  // key within tile
            int c4 = f & 15;
            float4 v = *(const float4*)(K + base + (size_t)(kt * 64 + r) * EE + c4 * 4);
            KVs[c4 * 4 + 0][r] = v.x;
            KVs[c4 * 4 + 1][r] = v.y;
            KVs[c4 * 4 + 2][r] = v.z;
            KVs[c4 * 4 + 3][r] = v.w;
        }
        __syncthreads();

        // S = Q K^T (4x4 per thread)
        float s[4][4];
#pragma unroll
        for (int i = 0; i < 4; i++)
#pragma unroll
            for (int j = 0; j < 4; j++) s[i][j] = 0.0f;

#pragma unroll 8
        for (int dd = 0; dd < 64; dd++) {
            float qv[4], kv[4];
#pragma unroll
            for (int i = 0; i < 4; i++) qv[i] = Qs[ty * 4 + i][dd];
#pragma unroll
            for (int j = 0; j < 4; j++) kv[j] = KVs[dd][tx * 4 + j];
#pragma unroll
            for (int i = 0; i < 4; i++)
#pragma unroll
                for (int j = 0; j < 4; j++)
                    s[i][j] = fmaf(qv[i], kv[j], s[i][j]);
        }

        // Online softmax per row (reduce across tx; 16-lane halves of warps)
#pragma unroll
        for (int i = 0; i < 4; i++) {
            float rmax = -1e30f;
#pragma unroll
            for (int j = 0; j < 4; j++) {
                s[i][j] *= scale;
                rmax = fmaxf(rmax, s[i][j]);
            }
#pragma unroll
            for (int mask = 8; mask >= 1; mask >>= 1)
                rmax = fmaxf(rmax, __shfl_xor_sync(0xffffffffu, rmax, mask));

            float mnew = fmaxf(m_i[i], rmax);
            float alpha = __expf(m_i[i] - mnew);
            float rsum = 0.0f;
#pragma unroll
            for (int j = 0; j < 4; j++) {
                float p = __expf(s[i][j] - mnew);
                Ps[ty * 4 + i][tx * 4 + j] = p;
                rsum += p;
            }
#pragma unroll
            for (int mask = 8; mask >= 1; mask >>= 1)
                rsum += __shfl_xor_sync(0xffffffffu, rsum, mask);

            l_i[i] = l_i[i] * alpha + rsum;
            m_i[i] = mnew;
#pragma unroll
            for (int j = 0; j < 4; j++) o[i][j] *= alpha;
        }
        __syncthreads();  // Ps visible; KVs (K) reads done

        // Load V tile natural layout: KVs[key][d]
#pragma unroll
        for (int l = 0; l < 4; l++) {
            int f = tid + l * 256;
            int r = f >> 4;
            int c4 = f & 15;
            float4 v = *(const float4*)(V + base + (size_t)(kt * 64 + r) * EE + c4 * 4);
            *(float4*)&KVs[r][c4 * 4] = v;
        }
        __syncthreads();

        // O += P @ V
#pragma unroll 8
        for (int c = 0; c < 64; c++) {
            float pv[4], vv[4];
#pragma unroll
            for (int i = 0; i < 4; i++) pv[i] = Ps[ty * 4 + i][c];
#pragma unroll
            for (int j = 0; j < 4; j++) vv[j] = KVs[c][tx * 4 + j];
#pragma unroll
            for (int i = 0; i < 4; i++)
#pragma unroll
                for (int j = 0; j < 4; j++)
                    o[i][j] = fmaf(pv[i], vv[j], o[i][j]);
        }
    }

    // Final normalize and store
#pragma unroll
    for (int i = 0; i < 4; i++) {
        float inv = 1.0f / l_i[i];
#pragma unroll
        for (int j = 0; j < 4; j++) {
            O[base + (size_t)(qt * 64 + ty * 4 + i) * EE + tx * 4 + j] = o[i][j] * inv;
        }
    }
}

// ---------------------------------------------------------------------------
// Launch
// Inputs (metadata order): query, key, value, Wq, bq, Wk, bk, Wv, bv, Wo, bo
// ---------------------------------------------------------------------------
extern "C" void kernel_launch(void* const* d_in, const int* in_sizes, int n_in,
                              void* d_out, int out_size)
{
    const float* query = (const float*)d_in[0];
    const float* key   = (const float*)d_in[1];
    const float* value = (const float*)d_in[2];
    const float* Wq    = (const float*)d_in[3];
    const float* bq    = (const float*)d_in[4];
    const float* Wk    = (const float*)d_in[5];
    const float* bk    = (const float*)d_in[6];
    const float* Wv    = (const float*)d_in[7];
    const float* bv    = (const float*)d_in[8];
    const float* Wo    = (const float*)d_in[9];
    const float* bo    = (const float*)d_in[10];
    float* out = (float*)d_out;

    float *Qb, *Kb, *Vb, *Ob;
    cudaGetSymbolAddress((void**)&Qb, g_Q);
    cudaGetSymbolAddress((void**)&Kb, g_K);
    cudaGetSymbolAddress((void**)&Vb, g_V);
    cudaGetSymbolAddress((void**)&Ob, g_O);

    dim3 ggrid(EE / 128, MROWS / 128);   // (8, 64)
    sgemm_bias_kernel<<<ggrid, 256>>>(query, Wq, bq, Qb, MROWS, EE, EE);
    sgemm_bias_kernel<<<ggrid, 256>>>(key,   Wk, bk, Kb, MROWS, EE, EE);
    sgemm_bias_kernel<<<ggrid, 256>>>(value, Wv, bv, Vb, MROWS, EE, EE);

    attn_kernel<<<dim3(TT / 64, BB * HH), 256>>>(Qb, Kb, Vb, Ob);

    sgemm_bias_kernel<<<ggrid, 256>>>(Ob, Wo, bo, out, MROWS, EE, EE);
}

// round 5
// speedup vs baseline: 1.7967x; 1.7967x over previous
#include <cuda_runtime.h>
#include <cuda_bf16.h>
#include <cstdint>

// Problem constants
#define BB 8
#define TT 1024
#define EE 1024
#define HH 16
#define DD 64
#define MROWS (BB * TT)   // 8192

// Scratch (allocation-free rule: __device__ globals)
__device__ float g_Q[MROWS * EE];
__device__ float g_K[MROWS * EE];
__device__ float g_V[MROWS * EE];
__device__ float g_O[MROWS * EE];

// ===========================================================================
// Helpers (target-agnostic PTX only: ldmatrix + mma.sync, sm_80+)
// ===========================================================================
__device__ __forceinline__ uint32_t smem_to_u32(const void* smem_ptr) {
    uint32_t addr;
    asm("{ .reg .u64 tmp; cvta.to.shared.u64 tmp, %1; cvt.u32.u64 %0, tmp; }"
        : "=r"(addr) : "l"(smem_ptr));
    return addr;
}

__device__ __forceinline__ void ldsm4(uint32_t* r, uint32_t addr) {
    asm volatile("ldmatrix.sync.aligned.m8n8.x4.shared.b16 {%0,%1,%2,%3}, [%4];"
                 : "=r"(r[0]), "=r"(r[1]), "=r"(r[2]), "=r"(r[3])
                 : "r"(addr));
}

__device__ __forceinline__ void mma16816(float* c, const uint32_t* a,
                                         uint32_t b0, uint32_t b1) {
    asm volatile(
        "mma.sync.aligned.m16n8k16.row.col.f32.bf16.bf16.f32 "
        "{%0,%1,%2,%3}, {%4,%5,%6,%7}, {%8,%9}, {%0,%1,%2,%3};"
        : "+f"(c[0]), "+f"(c[1]), "+f"(c[2]), "+f"(c[3])
        : "r"(a[0]), "r"(a[1]), "r"(a[2]), "r"(a[3]), "r"(b0), "r"(b1));
}

// ===========================================================================
// HMMA GEMM: Y[M,N] = X[M,K] @ W[N,K]^T + bias[N]   (M=8192, N=K=1024)
// Tile 128x128, BK=32, 256 threads = 8 warps (4x2), warp tile 32x64.
// Compensated bf16: hi = truncated fp32 top-16, lo = rn(residual); 3 MMAs.
// SMEM rows: 32 bf16 (64B) + 16B pad = 80B  -> ldmatrix conflict-free
// (granule = 5*row mod 8 is a permutation of 0..7).
// ===========================================================================
#define ROWB 80
#define MATB (128 * ROWB)             // 10240 B per matrix buffer
#define STAGEB (4 * MATB)             // Ah, Al, Bh, Bl  = 40960 B
#define GEMM_SMEM_BYTES (2 * STAGEB)  // 81920 B (epilogue reuses 65536 B)

// Split fp32x4 -> hi/lo bf16x4, store 8B each to smem buffers at byte off.
__device__ __forceinline__ void cvt_store4(float4 v, char* hibuf, char* lobuf,
                                           uint32_t off) {
    uint32_t ux = __float_as_uint(v.x), uy = __float_as_uint(v.y);
    uint32_t uz = __float_as_uint(v.z), uw = __float_as_uint(v.w);
    uint32_t h01 = __byte_perm(ux, uy, 0x7632);
    uint32_t h23 = __byte_perm(uz, uw, 0x7632);
    float lx = v.x - __uint_as_float(ux & 0xFFFF0000u);
    float ly = v.y - __uint_as_float(uy & 0xFFFF0000u);
    float lz = v.z - __uint_as_float(uz & 0xFFFF0000u);
    float lw = v.w - __uint_as_float(uw & 0xFFFF0000u);
    uint32_t l01, l23;
    asm("cvt.rn.bf16x2.f32 %0, %1, %2;" : "=r"(l01) : "f"(ly), "f"(lx));
    asm("cvt.rn.bf16x2.f32 %0, %1, %2;" : "=r"(l23) : "f"(lw), "f"(lz));
    *(uint2*)(hibuf + off) = make_uint2(h01, h23);
    *(uint2*)(lobuf + off) = make_uint2(l01, l23);
}

// Epilogue staging swizzle: 512B rows, rotate 16B chunks by row (bits 4-6).
__device__ __forceinline__ uint32_t ds_swz(int r, uint32_t cbytes) {
    return (uint32_t)r * 512u + (cbytes ^ (((uint32_t)r & 7u) << 4));
}

__global__ __launch_bounds__(256, 1) void gemm_tc_kernel(
    const float* __restrict__ X, const float* __restrict__ W,
    const float* __restrict__ bias, float* __restrict__ Y)
{
    extern __shared__ char smem[];
    const uint32_t sb = smem_to_u32(smem);
    const int tid = threadIdx.x;
    const int lane = tid & 31;
    const int wid = tid >> 5;
    const int wm = wid & 3;       // warp row 0..3 -> rows wm*32..+32
    const int wn = wid >> 2;      // warp col 0..1 -> cols wn*64..+64
    const int row0 = blockIdx.y * 128;
    const int col0 = blockIdx.x * 128;

    float acc[2][8][4];
#pragma unroll
    for (int mt = 0; mt < 2; mt++)
#pragma unroll
        for (int n8 = 0; n8 < 8; n8++)
#pragma unroll
            for (int q = 0; q < 4; q++) acc[mt][n8][q] = 0.0f;

    float4 ra[4], rb[4];

    // --- prologue: ldg + sts chunk 0 ---
#pragma unroll
    for (int l = 0; l < 4; l++) {
        int f = tid + l * 256;
        int r = f >> 3, c4 = f & 7;
        ra[l] = *(const float4*)(X + (size_t)(row0 + r) * EE + c4 * 4);
        rb[l] = *(const float4*)(W + (size_t)(col0 + r) * EE + c4 * 4);
    }
    {
        char* S = smem;   // stage 0
#pragma unroll
        for (int l = 0; l < 4; l++) {
            int f = tid + l * 256;
            int r = f >> 3, c4 = f & 7;
            uint32_t off = r * ROWB + c4 * 8;
            cvt_store4(ra[l], S, S + MATB, off);
            cvt_store4(rb[l], S + 2 * MATB, S + 3 * MATB, off);
        }
    }
    __syncthreads();

    const int lr = lane & 15;                  // ldmatrix row 0..15
    const uint32_t lk = (uint32_t)(lane >> 4) << 4;  // k-half byte offset 0/16

    for (int c = 0; c < 32; c++) {
        // prefetch next chunk to regs (hides LDG under MMAs)
        if (c < 31) {
#pragma unroll
            for (int l = 0; l < 4; l++) {
                int f = tid + l * 256;
                int r = f >> 3, c4 = f & 7;
                ra[l] = *(const float4*)(X + (size_t)(row0 + r) * EE +
                                         (c + 1) * 32 + c4 * 4);
                rb[l] = *(const float4*)(W + (size_t)(col0 + r) * EE +
                                         (c + 1) * 32 + c4 * 4);
            }
        }

        // compute on stage c&1
        {
            uint32_t SA = sb + (uint32_t)(c & 1) * STAGEB;
            uint32_t SB = SA + 2 * MATB;
#pragma unroll
            for (int kk = 0; kk < 2; kk++) {
                uint32_t kb = (uint32_t)kk * 32 + lk;
                uint32_t ah[2][4], al[2][4];
#pragma unroll
                for (int mt = 0; mt < 2; mt++) {
                    uint32_t addr = SA + (uint32_t)(wm * 32 + mt * 16 + lr) * ROWB + kb;
                    ldsm4(ah[mt], addr);
                    ldsm4(al[mt], addr + MATB);
                }
                uint32_t bh[4][4], bl[4][4];
#pragma unroll
                for (int nt = 0; nt < 4; nt++) {
                    uint32_t addr = SB + (uint32_t)(wn * 64 + nt * 16 + lr) * ROWB + kb;
                    ldsm4(bh[nt], addr);
                    ldsm4(bl[nt], addr + MATB);
                }
#pragma unroll
                for (int mt = 0; mt < 2; mt++) {
#pragma unroll
                    for (int n8 = 0; n8 < 8; n8++) {
                        int g = n8 >> 1, o = n8 & 1;
                        uint32_t b0 = bh[g][o], b1 = bh[g][o + 2];
                        uint32_t c0 = bl[g][o], c1 = bl[g][o + 2];
                        mma16816(acc[mt][n8], ah[mt], b0, b1);
                        mma16816(acc[mt][n8], ah[mt], c0, c1);
                        mma16816(acc[mt][n8], al[mt], b0, b1);
                    }
                }
            }
        }

        // store next chunk into other stage
        if (c < 31) {
            char* S = smem + ((c + 1) & 1) * STAGEB;
#pragma unroll
            for (int l = 0; l < 4; l++) {
                int f = tid + l * 256;
                int r = f >> 3, c4 = f & 7;
                uint32_t off = r * ROWB + c4 * 8;
                cvt_store4(ra[l], S, S + MATB, off);
                cvt_store4(rb[l], S + 2 * MATB, S + 3 * MATB, off);
            }
        }
        __syncthreads();
    }

    // --- epilogue: accums -> swizzled smem -> coalesced gmem + bias ---
    char* Ds = smem;
#pragma unroll
    for (int mt = 0; mt < 2; mt++) {
#pragma unroll
        for (int n8 = 0; n8 < 8; n8++) {
            int r = wm * 32 + mt * 16 + (lane >> 2);
            uint32_t cb = (uint32_t)(wn * 64 + n8 * 8 + (lane & 3) * 2) * 4u;
            *(float2*)(Ds + ds_swz(r, cb)) =
                make_float2(acc[mt][n8][0], acc[mt][n8][1]);
            *(float2*)(Ds + ds_swz(r + 8, cb)) =
                make_float2(acc[mt][n8][2], acc[mt][n8][3]);
        }
    }
    __syncthreads();

#pragma unroll
    for (int l = 0; l < 16; l++) {
        int f = tid + l * 256;
        int r = f >> 5;
        int c4 = f & 31;
        float4 d = *(float4*)(Ds + ds_swz(r, (uint32_t)c4 * 16u));
        float4 bv = *(const float4*)(bias + col0 + c4 * 4);
        d.x += bv.x; d.y += bv.y; d.z += bv.z; d.w += bv.w;
        *(float4*)(Y + (size_t)(row0 + r) * EE + col0 + c4 * 4) = d;
    }
}

// ===========================================================================
// Flash-attention kernel, fp32, LDS.128-friendly layouts.
// Grid: (T/128, B*H). Block 256 threads (16 ty x 16 tx).
// Thread microtile: 8 rows (ty*8..) x 4 cols (tx*4..).
// SMEM:
//   Qt [64 d][132]  transposed Q (q contiguous, padded)    8448 floats
//   Kt [64 d][64 k] transposed K; reused as Vs[64 k][64 d] 4096 floats
//   Ps [128 q][68]  natural P (float4 stores, broadcast reads) 8704 floats
// ===========================================================================
#define ATT_QS 132
#define ATT_PS 68
#define ATT_SMEM_FLOATS (64 * ATT_QS + 64 * 64 + 128 * ATT_PS)
#define ATT_SMEM_BYTES (ATT_SMEM_FLOATS * 4)

__global__ __launch_bounds__(256) void attn_kernel(
    const float* __restrict__ Q, const float* __restrict__ K,
    const float* __restrict__ V, float* __restrict__ O)
{
    extern __shared__ char smem_raw[];
    float* Qt = (float*)smem_raw;                 // [64][132]
    float* Kt = Qt + 64 * ATT_QS;                 // [64][64]
    float* Ps = Kt + 64 * 64;                     // [128][68]
    float* Vs = Kt;                               // reuse

    const int tid = threadIdx.x;
    const int tx = tid & 15;
    const int ty = tid >> 4;
    const int qt = blockIdx.x;
    const int bh = blockIdx.y;
    const int b = bh >> 4;
    const int h = bh & 15;
    const size_t base = ((size_t)b * TT) * EE + (size_t)h * DD;

    // Load Q tile (128 rows x 64 d) transposed: Qt[d][row]
#pragma unroll
    for (int l = 0; l < 8; l++) {
        int f = tid + l * 256;
        int r = f >> 4;
        int c4 = f & 15;
        float4 v = *(const float4*)(Q + base + (size_t)(qt * 128 + r) * EE + c4 * 4);
        Qt[(c4 * 4 + 0) * ATT_QS + r] = v.x;
        Qt[(c4 * 4 + 1) * ATT_QS + r] = v.y;
        Qt[(c4 * 4 + 2) * ATT_QS + r] = v.z;
        Qt[(c4 * 4 + 3) * ATT_QS + r] = v.w;
    }

    float m_i[8], l_i[8], o[8][4];
#pragma unroll
    for (int i = 0; i < 8; i++) {
        m_i[i] = -1e30f;
        l_i[i] = 0.0f;
#pragma unroll
        for (int j = 0; j < 4; j++) o[i][j] = 0.0f;
    }

    const float scale = 0.125f;  // 1/sqrt(64)

    for (int kt = 0; kt < 16; kt++) {
        __syncthreads();  // prior reads of Kt(as Vs)/Ps done

        // K tile transposed: Kt[d][key]
#pragma unroll
        for (int l = 0; l < 4; l++) {
            int f = tid + l * 256;
            int r = f >> 4;
            int c4 = f & 15;
            float4 v = *(const float4*)(K + base + (size_t)(kt * 64 + r) * EE + c4 * 4);
            Kt[(c4 * 4 + 0) * 64 + r] = v.x;
            Kt[(c4 * 4 + 1) * 64 + r] = v.y;
            Kt[(c4 * 4 + 2) * 64 + r] = v.z;
            Kt[(c4 * 4 + 3) * 64 + r] = v.w;
        }
        __syncthreads();

        // S = Q K^T : 8x4 per thread, all smem reads via LDS.128
        float s[8][4];
#pragma unroll
        for (int i = 0; i < 8; i++)
#pragma unroll
            for (int j = 0; j < 4; j++) s[i][j] = 0.0f;

#pragma unroll 4
        for (int dd = 0; dd < 64; dd++) {
            const float* qrow = Qt + dd * ATT_QS + ty * 8;
            float4 qa = *(const float4*)qrow;
            float4 qb = *(const float4*)(qrow + 4);
            float4 kv = *(const float4*)(Kt + dd * 64 + tx * 4);
            float q[8] = {qa.x, qa.y, qa.z, qa.w, qb.x, qb.y, qb.z, qb.w};
            float kk[4] = {kv.x, kv.y, kv.z, kv.w};
#pragma unroll
            for (int i = 0; i < 8; i++)
#pragma unroll
                for (int j = 0; j < 4; j++)
                    s[i][j] = fmaf(q[i], kk[j], s[i][j]);
        }

        // Online softmax, rows reduced across the 16 tx lanes
#pragma unroll
        for (int i = 0; i < 8; i++) {
            float rmax = -1e30f;
#pragma unroll
            for (int j = 0; j < 4; j++) {
                s[i][j] *= scale;
                rmax = fmaxf(rmax, s[i][j]);
            }
#pragma unroll
            for (int mask = 8; mask >= 1; mask >>= 1)
                rmax = fmaxf(rmax, __shfl_xor_sync(0xffffffffu, rmax, mask));

            float mnew = fmaxf(m_i[i], rmax);
            float alpha = __expf(m_i[i] - mnew);
            float pv[4];
            float rsum = 0.0f;
#pragma unroll
            for (int j = 0; j < 4; j++) {
                pv[j] = __expf(s[i][j] - mnew);
                rsum += pv[j];
            }
            // conflict-free float4 store (row stride 68 floats = 17*16B)
            *(float4*)&Ps[(ty * 8 + i) * ATT_PS + tx * 4] =
                make_float4(pv[0], pv[1], pv[2], pv[3]);
#pragma unroll
            for (int mask = 8; mask >= 1; mask >>= 1)
                rsum += __shfl_xor_sync(0xffffffffu, rsum, mask);

            l_i[i] = l_i[i] * alpha + rsum;
            m_i[i] = mnew;
#pragma unroll
            for (int j = 0; j < 4; j++) o[i][j] *= alpha;
        }
        __syncthreads();  // Ps visible; Kt reads done

        // V tile natural: Vs[key][d]
#pragma unroll
        for (int l = 0; l < 4; l++) {
            int f = tid + l * 256;
            int r = f >> 4;
            int c4 = f & 15;
            float4 v = *(const float4*)(V + base + (size_t)(kt * 64 + r) * EE + c4 * 4);
            *(float4*)&Vs[r * 64 + c4 * 4] = v;
        }
        __syncthreads();

        // O += P @ V : P via broadcast scalars, V via LDS.128
#pragma unroll 2
        for (int c = 0; c < 64; c++) {
            float4 vv = *(const float4*)(Vs + c * 64 + tx * 4);
            float pr[8];
#pragma unroll
            for (int i = 0; i < 8; i++) pr[i] = Ps[(ty * 8 + i) * ATT_PS + c];
            float vr[4] = {vv.x, vv.y, vv.z, vv.w};
#pragma unroll
            for (int i = 0; i < 8; i++)
#pragma unroll
                for (int j = 0; j < 4; j++)
                    o[i][j] = fmaf(pr[i], vr[j], o[i][j]);
        }
    }

    // Final normalize and store
#pragma unroll
    for (int i = 0; i < 8; i++) {
        float inv = 1.0f / l_i[i];
        float4 r = make_float4(o[i][0] * inv, o[i][1] * inv,
                               o[i][2] * inv, o[i][3] * inv);
        *(float4*)(O + base + (size_t)(qt * 128 + ty * 8 + i) * EE + tx * 4) = r;
    }
}

// ---------------------------------------------------------------------------
// Launch
// Inputs (metadata order): query, key, value, Wq, bq, Wk, bk, Wv, bv, Wo, bo
// ---------------------------------------------------------------------------
extern "C" void kernel_launch(void* const* d_in, const int* in_sizes, int n_in,
                              void* d_out, int out_size)
{
    const float* query = (const float*)d_in[0];
    const float* key   = (const float*)d_in[1];
    const float* value = (const float*)d_in[2];
    const float* Wq    = (const float*)d_in[3];
    const float* bq    = (const float*)d_in[4];
    const float* Wk    = (const float*)d_in[5];
    const float* bk    = (const float*)d_in[6];
    const float* Wv    = (const float*)d_in[7];
    const float* bv    = (const float*)d_in[8];
    const float* Wo    = (const float*)d_in[9];
    const float* bo    = (const float*)d_in[10];
    float* out = (float*)d_out;

    float *Qb, *Kb, *Vb, *Ob;
    cudaGetSymbolAddress((void**)&Qb, g_Q);
    cudaGetSymbolAddress((void**)&Kb, g_K);
    cudaGetSymbolAddress((void**)&Vb, g_V);
    cudaGetSymbolAddress((void**)&Ob, g_O);

    cudaFuncSetAttribute(gemm_tc_kernel,
                         cudaFuncAttributeMaxDynamicSharedMemorySize,
                         GEMM_SMEM_BYTES);
    cudaFuncSetAttribute(attn_kernel,
                         cudaFuncAttributeMaxDynamicSharedMemorySize,
                         ATT_SMEM_BYTES);

    dim3 ggrid(EE / 128, MROWS / 128);   // (8, 64)
    gemm_tc_kernel<<<ggrid, 256, GEMM_SMEM_BYTES>>>(query, Wq, bq, Qb);
    gemm_tc_kernel<<<ggrid, 256, GEMM_SMEM_BYTES>>>(key,   Wk, bk, Kb);
    gemm_tc_kernel<<<ggrid, 256, GEMM_SMEM_BYTES>>>(value, Wv, bv, Vb);

    attn_kernel<<<dim3(TT / 128, BB * HH), 256, ATT_SMEM_BYTES>>>(Qb, Kb, Vb, Ob);

    gemm_tc_kernel<<<ggrid, 256, GEMM_SMEM_BYTES>>>(Ob, Wo, bo, out);
}

// round 6
// speedup vs baseline: 2.4332x; 1.3543x over previous
#include <cuda_runtime.h>
#include <cuda_bf16.h>
#include <cstdint>

// Problem constants
#define BB 8
#define TT 1024
#define EE 1024
#define HH 16
#define DD 64
#define MROWS (BB * TT)   // 8192

// Scratch (allocation-free rule: __device__ globals)
__device__ float g_Q[MROWS * EE];
__device__ float g_K[MROWS * EE];
__device__ float g_V[MROWS * EE];
__device__ float g_O[MROWS * EE];

// ===========================================================================
// Helpers (target-agnostic PTX only: ldmatrix + mma.sync, sm_80+)
// ===========================================================================
__device__ __forceinline__ uint32_t smem_to_u32(const void* smem_ptr) {
    uint32_t addr;
    asm("{ .reg .u64 tmp; cvta.to.shared.u64 tmp, %1; cvt.u32.u64 %0, tmp; }"
        : "=r"(addr) : "l"(smem_ptr));
    return addr;
}

__device__ __forceinline__ void ldsm4(uint32_t* r, uint32_t addr) {
    asm volatile("ldmatrix.sync.aligned.m8n8.x4.shared.b16 {%0,%1,%2,%3}, [%4];"
                 : "=r"(r[0]), "=r"(r[1]), "=r"(r[2]), "=r"(r[3])
                 : "r"(addr));
}

__device__ __forceinline__ void mma16816(float* c, const uint32_t* a,
                                         uint32_t b0, uint32_t b1) {
    asm volatile(
        "mma.sync.aligned.m16n8k16.row.col.f32.bf16.bf16.f32 "
        "{%0,%1,%2,%3}, {%4,%5,%6,%7}, {%8,%9}, {%0,%1,%2,%3};"
        : "+f"(c[0]), "+f"(c[1]), "+f"(c[2]), "+f"(c[3])
        : "r"(a[0]), "r"(a[1]), "r"(a[2]), "r"(a[3]), "r"(b0), "r"(b1));
}

// ===========================================================================
// HMMA GEMM: Y[M,N] = X[M,K] @ W[N,K]^T + bias[N]   (M=8192, N=K=1024)
// Tile 128x128, BK=32, 256 threads = 8 warps (4x2), warp tile 32x64.
// Compensated bf16: hi = truncated fp32 top-16, lo = rn(residual); 3 MMAs.
// SMEM rows: 32 bf16 (64B) + 16B pad = 80B -> ldmatrix conflict-free.
// ===========================================================================
#define ROWB 80
#define MATB (128 * ROWB)             // 10240 B per matrix buffer
#define STAGEB (4 * MATB)             // Ah, Al, Bh, Bl  = 40960 B
#define GEMM_SMEM_BYTES (2 * STAGEB)  // 81920 B (epilogue reuses 65536 B)

// Split fp32x4 -> hi/lo bf16x4, store 8B each to smem buffers at byte off.
__device__ __forceinline__ void cvt_store4(float4 v, char* hibuf, char* lobuf,
                                           uint32_t off) {
    uint32_t ux = __float_as_uint(v.x), uy = __float_as_uint(v.y);
    uint32_t uz = __float_as_uint(v.z), uw = __float_as_uint(v.w);
    uint32_t h01 = __byte_perm(ux, uy, 0x7632);
    uint32_t h23 = __byte_perm(uz, uw, 0x7632);
    float lx = v.x - __uint_as_float(ux & 0xFFFF0000u);
    float ly = v.y - __uint_as_float(uy & 0xFFFF0000u);
    float lz = v.z - __uint_as_float(uz & 0xFFFF0000u);
    float lw = v.w - __uint_as_float(uw & 0xFFFF0000u);
    uint32_t l01, l23;
    asm("cvt.rn.bf16x2.f32 %0, %1, %2;" : "=r"(l01) : "f"(ly), "f"(lx));
    asm("cvt.rn.bf16x2.f32 %0, %1, %2;" : "=r"(l23) : "f"(lw), "f"(lz));
    *(uint2*)(hibuf + off) = make_uint2(h01, h23);
    *(uint2*)(lobuf + off) = make_uint2(l01, l23);
}

// Epilogue staging swizzle: 512B rows, rotate 16B chunks by row (bits 4-6).
__device__ __forceinline__ uint32_t ds_swz(int r, uint32_t cbytes) {
    return (uint32_t)r * 512u + (cbytes ^ (((uint32_t)r & 7u) << 4));
}

__global__ __launch_bounds__(256, 1) void gemm_tc_kernel(
    const float* __restrict__ X, const float* __restrict__ W,
    const float* __restrict__ bias, float* __restrict__ Y)
{
    extern __shared__ char smem[];
    const uint32_t sb = smem_to_u32(smem);
    const int tid = threadIdx.x;
    const int lane = tid & 31;
    const int wid = tid >> 5;
    const int wm = wid & 3;
    const int wn = wid >> 2;
    const int row0 = blockIdx.y * 128;
    const int col0 = blockIdx.x * 128;

    float acc[2][8][4];
#pragma unroll
    for (int mt = 0; mt < 2; mt++)
#pragma unroll
        for (int n8 = 0; n8 < 8; n8++)
#pragma unroll
            for (int q = 0; q < 4; q++) acc[mt][n8][q] = 0.0f;

    float4 ra[4], rb[4];

#pragma unroll
    for (int l = 0; l < 4; l++) {
        int f = tid + l * 256;
        int r = f >> 3, c4 = f & 7;
        ra[l] = *(const float4*)(X + (size_t)(row0 + r) * EE + c4 * 4);
        rb[l] = *(const float4*)(W + (size_t)(col0 + r) * EE + c4 * 4);
    }
    {
        char* S = smem;
#pragma unroll
        for (int l = 0; l < 4; l++) {
            int f = tid + l * 256;
            int r = f >> 3, c4 = f & 7;
            uint32_t off = r * ROWB + c4 * 8;
            cvt_store4(ra[l], S, S + MATB, off);
            cvt_store4(rb[l], S + 2 * MATB, S + 3 * MATB, off);
        }
    }
    __syncthreads();

    const int lr = lane & 15;
    const uint32_t lk = (uint32_t)(lane >> 4) << 4;

    for (int c = 0; c < 32; c++) {
        if (c < 31) {
#pragma unroll
            for (int l = 0; l < 4; l++) {
                int f = tid + l * 256;
                int r = f >> 3, c4 = f & 7;
                ra[l] = *(const float4*)(X + (size_t)(row0 + r) * EE +
                                         (c + 1) * 32 + c4 * 4);
                rb[l] = *(const float4*)(W + (size_t)(col0 + r) * EE +
                                         (c + 1) * 32 + c4 * 4);
            }
        }

        {
            uint32_t SA = sb + (uint32_t)(c & 1) * STAGEB;
            uint32_t SB = SA + 2 * MATB;
#pragma unroll
            for (int kk = 0; kk < 2; kk++) {
                uint32_t kb = (uint32_t)kk * 32 + lk;
                uint32_t ah[2][4], al[2][4];
#pragma unroll
                for (int mt = 0; mt < 2; mt++) {
                    uint32_t addr = SA + (uint32_t)(wm * 32 + mt * 16 + lr) * ROWB + kb;
                    ldsm4(ah[mt], addr);
                    ldsm4(al[mt], addr + MATB);
                }
                uint32_t bh[4][4], bl[4][4];
#pragma unroll
                for (int nt = 0; nt < 4; nt++) {
                    uint32_t addr = SB + (uint32_t)(wn * 64 + nt * 16 + lr) * ROWB + kb;
                    ldsm4(bh[nt], addr);
                    ldsm4(bl[nt], addr + MATB);
                }
#pragma unroll
                for (int mt = 0; mt < 2; mt++) {
#pragma unroll
                    for (int n8 = 0; n8 < 8; n8++) {
                        int g = n8 >> 1, o = n8 & 1;
                        uint32_t b0 = bh[g][o], b1 = bh[g][o + 2];
                        uint32_t c0 = bl[g][o], c1 = bl[g][o + 2];
                        mma16816(acc[mt][n8], ah[mt], b0, b1);
                        mma16816(acc[mt][n8], ah[mt], c0, c1);
                        mma16816(acc[mt][n8], al[mt], b0, b1);
                    }
                }
            }
        }

        if (c < 31) {
            char* S = smem + ((c + 1) & 1) * STAGEB;
#pragma unroll
            for (int l = 0; l < 4; l++) {
                int f = tid + l * 256;
                int r = f >> 3, c4 = f & 7;
                uint32_t off = r * ROWB + c4 * 8;
                cvt_store4(ra[l], S, S + MATB, off);
                cvt_store4(rb[l], S + 2 * MATB, S + 3 * MATB, off);
            }
        }
        __syncthreads();
    }

    char* Ds = smem;
#pragma unroll
    for (int mt = 0; mt < 2; mt++) {
#pragma unroll
        for (int n8 = 0; n8 < 8; n8++) {
            int r = wm * 32 + mt * 16 + (lane >> 2);
            uint32_t cb = (uint32_t)(wn * 64 + n8 * 8 + (lane & 3) * 2) * 4u;
            *(float2*)(Ds + ds_swz(r, cb)) =
                make_float2(acc[mt][n8][0], acc[mt][n8][1]);
            *(float2*)(Ds + ds_swz(r + 8, cb)) =
                make_float2(acc[mt][n8][2], acc[mt][n8][3]);
        }
    }
    __syncthreads();

#pragma unroll
    for (int l = 0; l < 16; l++) {
        int f = tid + l * 256;
        int r = f >> 5;
        int c4 = f & 31;
        float4 d = *(float4*)(Ds + ds_swz(r, (uint32_t)c4 * 16u));
        float4 bv = *(const float4*)(bias + col0 + c4 * 4);
        d.x += bv.x; d.y += bv.y; d.z += bv.z; d.w += bv.w;
        *(float4*)(Y + (size_t)(row0 + r) * EE + col0 + c4 * 4) = d;
    }
}

// ===========================================================================
// Tensor-core flash attention. Grid (T/128, B*H), 256 threads = 8 warps.
// Warp w owns q-rows w*16..w*16+15. Key chunks of 64.
// All matmuls via mma.m16n8k16 bf16 with hi/lo compensation (3 mmas each).
// S C-fragment == P A-fragment layout -> P stays in registers.
// SMEM (144B row stride = 9*16B -> conflict-free ldmatrix):
//   Qh,Ql: 128 q-rows x 64 d          (Q pre-scaled by 0.125)
//   Kh,Kl: 64 key-rows x 64 d
//   Vh,Vl: 64 d-rows x 64 keys (transposed during load)
// ===========================================================================
#define AROWB 144
#define A_QH 0
#define A_QL (128 * AROWB)
#define A_KH (2 * 128 * AROWB)
#define A_KL (A_KH + 64 * AROWB)
#define A_VH (A_KH + 2 * 64 * AROWB)
#define A_VL (A_VH + 64 * AROWB)
#define ATT_SMEM_BYTES (A_VL + 64 * AROWB)   // 73728

// Pack pair (x0 = even idx, x1 = odd idx) -> hi bf16x2, lo bf16x2.
__device__ __forceinline__ void pack_p(float x0, float x1, uint32_t& hi,
                                       uint32_t& lo) {
    uint32_t u0 = __float_as_uint(x0), u1 = __float_as_uint(x1);
    hi = __byte_perm(u0, u1, 0x7632);
    float l0 = x0 - __uint_as_float(u0 & 0xFFFF0000u);
    float l1 = x1 - __uint_as_float(u1 & 0xFFFF0000u);
    asm("cvt.rn.bf16x2.f32 %0, %1, %2;" : "=r"(lo) : "f"(l1), "f"(l0));
}

__global__ __launch_bounds__(256, 1) void attn_tc_kernel(
    const float* __restrict__ Q, const float* __restrict__ K,
    const float* __restrict__ V, float* __restrict__ O)
{
    extern __shared__ char sm[];
    const uint32_t sb = smem_to_u32(sm);
    const int tid = threadIdx.x;
    const int lane = tid & 31;
    const int wid = tid >> 5;
    const int qt = blockIdx.x;
    const int bh = blockIdx.y;
    const int b = bh >> 4;
    const int h = bh & 15;
    const size_t base = ((size_t)b * TT) * EE + (size_t)h * DD;

    const int lr = lane & 15;
    const uint32_t lk = (uint32_t)(lane >> 4) << 4;
    const int quad = lane >> 2;
    const int c2 = (lane & 3) * 2;

    // Load Q tile (128 x 64), pre-scaled by 1/sqrt(D)=0.125, hi/lo split.
#pragma unroll
    for (int l = 0; l < 8; l++) {
        int f = tid + l * 256;
        int r = f >> 4;
        int c4 = f & 15;
        float4 v = *(const float4*)(Q + base + (size_t)(qt * 128 + r) * EE + c4 * 4);
        v.x *= 0.125f; v.y *= 0.125f; v.z *= 0.125f; v.w *= 0.125f;
        cvt_store4(v, sm + A_QH, sm + A_QL, r * AROWB + c4 * 8);
    }

    float o_acc[8][4];
#pragma unroll
    for (int n8 = 0; n8 < 8; n8++)
#pragma unroll
        for (int q = 0; q < 4; q++) o_acc[n8][q] = 0.0f;
    float m0 = -1e30f, m1 = -1e30f, l0 = 0.0f, l1 = 0.0f;

    for (int kt = 0; kt < 16; kt++) {
        __syncthreads();   // prior chunk's K/V reads done (covers Q for kt=0)

        // K chunk (64 x 64), hi/lo
#pragma unroll
        for (int l = 0; l < 4; l++) {
            int f = tid + l * 256;
            int r = f >> 4;
            int c4 = f & 15;
            float4 v = *(const float4*)(K + base + (size_t)(kt * 64 + r) * EE + c4 * 4);
            cvt_store4(v, sm + A_KH, sm + A_KL, r * AROWB + c4 * 8);
        }
        // V chunk transposed to [d][key], hi/lo
#pragma unroll
        for (int l = 0; l < 4; l++) {
            int f = tid + l * 256;
            int r = f >> 4;     // key
            int c4 = f & 15;
            float4 v = *(const float4*)(V + base + (size_t)(kt * 64 + r) * EE + c4 * 4);
            float vals[4] = {v.x, v.y, v.z, v.w};
#pragma unroll
            for (int j = 0; j < 4; j++) {
                int d = c4 * 4 + j;
                uint32_t u = __float_as_uint(vals[j]);
                *(uint16_t*)(sm + A_VH + d * AROWB + r * 2) = (uint16_t)(u >> 16);
                float lo = vals[j] - __uint_as_float(u & 0xFFFF0000u);
                *(__nv_bfloat16*)(sm + A_VL + d * AROWB + r * 2) = __float2bfloat16(lo);
            }
        }
        __syncthreads();

        // ---- S = (Q*scale) K^T  (128x64 per CTA; warp: 16x64) ----
        float s[8][4];
#pragma unroll
        for (int n8 = 0; n8 < 8; n8++)
#pragma unroll
            for (int q = 0; q < 4; q++) s[n8][q] = 0.0f;

#pragma unroll
        for (int kk = 0; kk < 4; kk++) {
            uint32_t kb = (uint32_t)kk * 32 + lk;
            uint32_t qh[4], ql[4];
            {
                uint32_t addr = sb + (uint32_t)(wid * 16 + lr) * AROWB + kb;
                ldsm4(qh, addr + A_QH);
                ldsm4(ql, addr + A_QL);
            }
            uint32_t kh[4][4], klo[4][4];
#pragma unroll
            for (int nt = 0; nt < 4; nt++) {
                uint32_t addr = sb + (uint32_t)(nt * 16 + lr) * AROWB + kb;
                ldsm4(kh[nt], addr + A_KH);
                ldsm4(klo[nt], addr + A_KL);
            }
#pragma unroll
            for (int n8 = 0; n8 < 8; n8++) {
                int g = n8 >> 1, o = n8 & 1;
                uint32_t b0 = kh[g][o], b1 = kh[g][o + 2];
                uint32_t c0 = klo[g][o], c1 = klo[g][o + 2];
                mma16816(s[n8], qh, b0, b1);
                mma16816(s[n8], qh, c0, c1);
                mma16816(s[n8], ql, b0, b1);
            }
        }

        // ---- online softmax on register fragments ----
        float rmax0 = -1e30f, rmax1 = -1e30f;
#pragma unroll
        for (int n8 = 0; n8 < 8; n8++) {
            rmax0 = fmaxf(rmax0, fmaxf(s[n8][0], s[n8][1]));
            rmax1 = fmaxf(rmax1, fmaxf(s[n8][2], s[n8][3]));
        }
#pragma unroll
        for (int mask = 1; mask <= 2; mask <<= 1) {
            rmax0 = fmaxf(rmax0, __shfl_xor_sync(0xffffffffu, rmax0, mask));
            rmax1 = fmaxf(rmax1, __shfl_xor_sync(0xffffffffu, rmax1, mask));
        }
        float mn0 = fmaxf(m0, rmax0), mn1 = fmaxf(m1, rmax1);
        float a0 = __expf(m0 - mn0), a1 = __expf(m1 - mn1);
        float sum0 = 0.0f, sum1 = 0.0f;
#pragma unroll
        for (int n8 = 0; n8 < 8; n8++) {
            s[n8][0] = __expf(s[n8][0] - mn0);
            s[n8][1] = __expf(s[n8][1] - mn0);
            s[n8][2] = __expf(s[n8][2] - mn1);
            s[n8][3] = __expf(s[n8][3] - mn1);
            sum0 += s[n8][0] + s[n8][1];
            sum1 += s[n8][2] + s[n8][3];
        }
#pragma unroll
        for (int mask = 1; mask <= 2; mask <<= 1) {
            sum0 += __shfl_xor_sync(0xffffffffu, sum0, mask);
            sum1 += __shfl_xor_sync(0xffffffffu, sum1, mask);
        }
        l0 = l0 * a0 + sum0; m0 = mn0;
        l1 = l1 * a1 + sum1; m1 = mn1;
#pragma unroll
        for (int n8 = 0; n8 < 8; n8++) {
            o_acc[n8][0] *= a0; o_acc[n8][1] *= a0;
            o_acc[n8][2] *= a1; o_acc[n8][3] *= a1;
        }

        // ---- O += P V  (P from registers; V^T from smem) ----
#pragma unroll
        for (int k = 0; k < 4; k++) {
            // P A-fragment for keys 16k..16k+15 (C-frag == A-frag layout)
            uint32_t ph[4], pl[4];
            pack_p(s[2 * k][0],     s[2 * k][1],     ph[0], pl[0]);
            pack_p(s[2 * k][2],     s[2 * k][3],     ph[1], pl[1]);
            pack_p(s[2 * k + 1][0], s[2 * k + 1][1], ph[2], pl[2]);
            pack_p(s[2 * k + 1][2], s[2 * k + 1][3], ph[3], pl[3]);

            uint32_t kb = (uint32_t)k * 32 + lk;   // key-byte offset in V rows
            uint32_t vh[4][4], vl[4][4];
#pragma unroll
            for (int nt = 0; nt < 4; nt++) {
                uint32_t addr = sb + (uint32_t)(nt * 16 + lr) * AROWB + kb;
                ldsm4(vh[nt], addr + A_VH);
                ldsm4(vl[nt], addr + A_VL);
            }
#pragma unroll
            for (int n8 = 0; n8 < 8; n8++) {
                int g = n8 >> 1, o = n8 & 1;
                uint32_t b0 = vh[g][o], b1 = vh[g][o + 2];
                uint32_t c0 = vl[g][o], c1 = vl[g][o + 2];
                mma16816(o_acc[n8], ph, b0, b1);
                mma16816(o_acc[n8], ph, c0, c1);
                mma16816(o_acc[n8], pl, b0, b1);
            }
        }
    }

    // ---- epilogue: normalize and store ----
    float inv0 = 1.0f / l0, inv1 = 1.0f / l1;
    size_t r0g = base + (size_t)(qt * 128 + wid * 16 + quad) * EE;
    size_t r1g = r0g + (size_t)8 * EE;
#pragma unroll
    for (int n8 = 0; n8 < 8; n8++) {
        int col = n8 * 8 + c2;
        *(float2*)(O + r0g + col) = make_float2(o_acc[n8][0] * inv0,
                                                o_acc[n8][1] * inv0);
        *(float2*)(O + r1g + col) = make_float2(o_acc[n8][2] * inv1,
                                                o_acc[n8][3] * inv1);
    }
}

// ---------------------------------------------------------------------------
// Launch
// Inputs (metadata order): query, key, value, Wq, bq, Wk, bk, Wv, bv, Wo, bo
// ---------------------------------------------------------------------------
extern "C" void kernel_launch(void* const* d_in, const int* in_sizes, int n_in,
                              void* d_out, int out_size)
{
    const float* query = (const float*)d_in[0];
    const float* key   = (const float*)d_in[1];
    const float* value = (const float*)d_in[2];
    const float* Wq    = (const float*)d_in[3];
    const float* bq    = (const float*)d_in[4];
    const float* Wk    = (const float*)d_in[5];
    const float* bk    = (const float*)d_in[6];
    const float* Wv    = (const float*)d_in[7];
    const float* bv    = (const float*)d_in[8];
    const float* Wo    = (const float*)d_in[9];
    const float* bo    = (const float*)d_in[10];
    float* out = (float*)d_out;

    float *Qb, *Kb, *Vb, *Ob;
    cudaGetSymbolAddress((void**)&Qb, g_Q);
    cudaGetSymbolAddress((void**)&Kb, g_K);
    cudaGetSymbolAddress((void**)&Vb, g_V);
    cudaGetSymbolAddress((void**)&Ob, g_O);

    cudaFuncSetAttribute(gemm_tc_kernel,
                         cudaFuncAttributeMaxDynamicSharedMemorySize,
                         GEMM_SMEM_BYTES);
    cudaFuncSetAttribute(attn_tc_kernel,
                         cudaFuncAttributeMaxDynamicSharedMemorySize,
                         ATT_SMEM_BYTES);

    dim3 ggrid(EE / 128, MROWS / 128);   // (8, 64)
    gemm_tc_kernel<<<ggrid, 256, GEMM_SMEM_BYTES>>>(query, Wq, bq, Qb);
    gemm_tc_kernel<<<ggrid, 256, GEMM_SMEM_BYTES>>>(key,   Wk, bk, Kb);
    gemm_tc_kernel<<<ggrid, 256, GEMM_SMEM_BYTES>>>(value, Wv, bv, Vb);

    attn_tc_kernel<<<dim3(TT / 128, BB * HH), 256, ATT_SMEM_BYTES>>>(Qb, Kb, Vb, Ob);

    gemm_tc_kernel<<<ggrid, 256, GEMM_SMEM_BYTES>>>(Ob, Wo, bo, out);
}

// round 7
// speedup vs baseline: 2.8270x; 1.1618x over previous
#include <cuda_runtime.h>
#include <cuda_bf16.h>
#include <cstdint>

// Problem constants
#define BB 8
#define TT 1024
#define EE 1024
#define HH 16
#define DD 64
#define MROWS (BB * TT)   // 8192
#define NELEM (MROWS * EE)

// Scratch (allocation-free rule: __device__ globals) — all bf16 hi/lo pairs
__device__ __nv_bfloat16 g_Qh[NELEM], g_Ql[NELEM];
__device__ __nv_bfloat16 g_Kh[NELEM], g_Kl[NELEM];
__device__ __nv_bfloat16 g_Vh[NELEM], g_Vl[NELEM];
__device__ __nv_bfloat16 g_Oh[NELEM], g_Ol[NELEM];
__device__ __nv_bfloat16 g_Xh[NELEM], g_Xl[NELEM];        // prepass input split
__device__ __nv_bfloat16 g_Wh[EE * EE], g_Wl[EE * EE];    // prepass weight split

// ===========================================================================
// Helpers (target-agnostic PTX: ldmatrix / mma.sync / cp.async, sm_80+)
// ===========================================================================
__device__ __forceinline__ uint32_t smem_to_u32(const void* smem_ptr) {
    uint32_t addr;
    asm("{ .reg .u64 tmp; cvta.to.shared.u64 tmp, %1; cvt.u32.u64 %0, tmp; }"
        : "=r"(addr) : "l"(smem_ptr));
    return addr;
}

__device__ __forceinline__ void ldsm4(uint32_t* r, uint32_t addr) {
    asm volatile("ldmatrix.sync.aligned.m8n8.x4.shared.b16 {%0,%1,%2,%3}, [%4];"
                 : "=r"(r[0]), "=r"(r[1]), "=r"(r[2]), "=r"(r[3])
                 : "r"(addr));
}

__device__ __forceinline__ void ldsm4t(uint32_t* r, uint32_t addr) {
    asm volatile("ldmatrix.sync.aligned.m8n8.x4.trans.shared.b16 {%0,%1,%2,%3}, [%4];"
                 : "=r"(r[0]), "=r"(r[1]), "=r"(r[2]), "=r"(r[3])
                 : "r"(addr));
}

__device__ __forceinline__ void mma16816(float* c, const uint32_t* a,
                                         uint32_t b0, uint32_t b1) {
    asm volatile(
        "mma.sync.aligned.m16n8k16.row.col.f32.bf16.bf16.f32 "
        "{%0,%1,%2,%3}, {%4,%5,%6,%7}, {%8,%9}, {%0,%1,%2,%3};"
        : "+f"(c[0]), "+f"(c[1]), "+f"(c[2]), "+f"(c[3])
        : "r"(a[0]), "r"(a[1]), "r"(a[2]), "r"(a[3]), "r"(b0), "r"(b1));
}

__device__ __forceinline__ void cp16(uint32_t dst, const void* src) {
    asm volatile("cp.async.cg.shared.global [%0], [%1], 16;"
                 :: "r"(dst), "l"(src));
}
#define CP_COMMIT() asm volatile("cp.async.commit_group;" ::: "memory")
#define CP_WAIT(n)  asm volatile("cp.async.wait_group %0;" :: "n"(n) : "memory")

// Split fp32 pair -> hi bf16x2 (truncated) + lo bf16x2 (rn residual).
__device__ __forceinline__ void pack_p(float x0, float x1, uint32_t& hi,
                                       uint32_t& lo) {
    uint32_t u0 = __float_as_uint(x0), u1 = __float_as_uint(x1);
    hi = __byte_perm(u0, u1, 0x7632);
    float l0 = x0 - __uint_as_float(u0 & 0xFFFF0000u);
    float l1 = x1 - __uint_as_float(u1 & 0xFFFF0000u);
    asm("cvt.rn.bf16x2.f32 %0, %1, %2;" : "=r"(lo) : "f"(l1), "f"(l0));
}

__device__ __forceinline__ void split4(float4 v, uint2& hi, uint2& lo) {
    uint32_t h0, l0, h1, l1;
    pack_p(v.x, v.y, h0, l0);
    pack_p(v.z, v.w, h1, l1);
    hi = make_uint2(h0, h1);
    lo = make_uint2(l0, l1);
}

// ===========================================================================
// Prepass: split fp32 array into hi/lo bf16 arrays (bandwidth-bound).
// ===========================================================================
__global__ __launch_bounds__(256) void split_kernel(
    const float4* __restrict__ x, uint2* __restrict__ hi,
    uint2* __restrict__ lo, int n4)
{
    int i = blockIdx.x * blockDim.x + threadIdx.x;
    if (i < n4) {
        uint2 h, l;
        split4(x[i], h, l);
        hi[i] = h;
        lo[i] = l;
    }
}

// ===========================================================================
// HMMA GEMM on pre-split bf16: Y[M,N] = X @ W^T + bias (M=8192, N=K=1024)
// Tile 128x128, BK=32, 256 threads = 8 warps (4x2), warp tile 32x64.
// 2-stage cp.async pipeline. SMEM rows 80B (64B data + 16B pad).
// mode 0: write fp32 Y. mode 1: write hi/lo bf16 (scaled).
// ===========================================================================
#define ROWB 80
#define MATB (128 * ROWB)             // 10240 B per matrix buffer
#define STAGEB (4 * MATB)             // Ah, Al, Bh, Bl = 40960 B
#define GEMM_SMEM_BYTES (2 * STAGEB)  // 81920 B

__device__ __forceinline__ uint32_t ds_swz(int r, uint32_t cbytes) {
    return (uint32_t)r * 512u + (cbytes ^ (((uint32_t)r & 7u) << 4));
}

__global__ __launch_bounds__(256, 2) void gemm_bf_kernel(
    const __nv_bfloat16* __restrict__ Ah, const __nv_bfloat16* __restrict__ Al,
    const __nv_bfloat16* __restrict__ Bh, const __nv_bfloat16* __restrict__ Bl,
    const float* __restrict__ bias, float scale, int mode,
    float* __restrict__ Yf, __nv_bfloat16* __restrict__ Yh,
    __nv_bfloat16* __restrict__ Yl)
{
    extern __shared__ char smem[];
    const uint32_t sb = smem_to_u32(smem);
    const int tid = threadIdx.x;
    const int lane = tid & 31;
    const int wid = tid >> 5;
    const int wm = wid & 3;
    const int wn = wid >> 2;
    const int row0 = blockIdx.y * 128;
    const int col0 = blockIdx.x * 128;

    float acc[2][8][4];
#pragma unroll
    for (int mt = 0; mt < 2; mt++)
#pragma unroll
        for (int n8 = 0; n8 < 8; n8++)
#pragma unroll
            for (int q = 0; q < 4; q++) acc[mt][n8][q] = 0.0f;

    // prologue: async-load chunk 0 into stage 0
    {
        uint32_t S = sb;
#pragma unroll
        for (int l = 0; l < 2; l++) {
            int f = tid + l * 256;
            int r = f >> 2, c16 = f & 3;
            uint32_t d = S + (uint32_t)r * ROWB + c16 * 16;
            size_t offA = (size_t)(row0 + r) * EE + c16 * 8;
            size_t offB = (size_t)(col0 + r) * EE + c16 * 8;
            cp16(d, Ah + offA);
            cp16(d + MATB, Al + offA);
            cp16(d + 2 * MATB, Bh + offB);
            cp16(d + 3 * MATB, Bl + offB);
        }
        CP_COMMIT();
    }

    const int lr = lane & 15;
    const uint32_t lk = (uint32_t)(lane >> 4) << 4;

    for (int c = 0; c < 32; c++) {
        if (c < 31) {
            uint32_t S = sb + (uint32_t)((c + 1) & 1) * STAGEB;
#pragma unroll
            for (int l = 0; l < 2; l++) {
                int f = tid + l * 256;
                int r = f >> 2, c16 = f & 3;
                uint32_t d = S + (uint32_t)r * ROWB + c16 * 16;
                size_t offA = (size_t)(row0 + r) * EE + (c + 1) * 32 + c16 * 8;
                size_t offB = (size_t)(col0 + r) * EE + (c + 1) * 32 + c16 * 8;
                cp16(d, Ah + offA);
                cp16(d + MATB, Al + offA);
                cp16(d + 2 * MATB, Bh + offB);
                cp16(d + 3 * MATB, Bl + offB);
            }
            CP_COMMIT();
            CP_WAIT(1);
        } else {
            CP_WAIT(0);
        }
        __syncthreads();

        {
            uint32_t SA = sb + (uint32_t)(c & 1) * STAGEB;
            uint32_t SB = SA + 2 * MATB;
#pragma unroll
            for (int kk = 0; kk < 2; kk++) {
                uint32_t kb = (uint32_t)kk * 32 + lk;
                uint32_t ah[2][4], al[2][4];
#pragma unroll
                for (int mt = 0; mt < 2; mt++) {
                    uint32_t addr = SA + (uint32_t)(wm * 32 + mt * 16 + lr) * ROWB + kb;
                    ldsm4(ah[mt], addr);
                    ldsm4(al[mt], addr + MATB);
                }
                uint32_t bh[4][4], bl[4][4];
#pragma unroll
                for (int nt = 0; nt < 4; nt++) {
                    uint32_t addr = SB + (uint32_t)(wn * 64 + nt * 16 + lr) * ROWB + kb;
                    ldsm4(bh[nt], addr);
                    ldsm4(bl[nt], addr + MATB);
                }
#pragma unroll
                for (int mt = 0; mt < 2; mt++) {
#pragma unroll
                    for (int n8 = 0; n8 < 8; n8++) {
                        int g = n8 >> 1, o = n8 & 1;
                        uint32_t b0 = bh[g][o], b1 = bh[g][o + 2];
                        uint32_t c0 = bl[g][o], c1 = bl[g][o + 2];
                        mma16816(acc[mt][n8], ah[mt], b0, b1);
                        mma16816(acc[mt][n8], ah[mt], c0, c1);
                        mma16816(acc[mt][n8], al[mt], b0, b1);
                    }
                }
            }
        }
        __syncthreads();
    }

    // epilogue: stage fp32 in swizzled smem, then coalesced output
    char* Ds = smem;
#pragma unroll
    for (int mt = 0; mt < 2; mt++) {
#pragma unroll
        for (int n8 = 0; n8 < 8; n8++) {
            int r = wm * 32 + mt * 16 + (lane >> 2);
            uint32_t cb = (uint32_t)(wn * 64 + n8 * 8 + (lane & 3) * 2) * 4u;
            *(float2*)(Ds + ds_swz(r, cb)) =
                make_float2(acc[mt][n8][0], acc[mt][n8][1]);
            *(float2*)(Ds + ds_swz(r + 8, cb)) =
                make_float2(acc[mt][n8][2], acc[mt][n8][3]);
        }
    }
    __syncthreads();

#pragma unroll
    for (int l = 0; l < 16; l++) {
        int f = tid + l * 256;
        int r = f >> 5;
        int c4 = f & 31;
        float4 d = *(float4*)(Ds + ds_swz(r, (uint32_t)c4 * 16u));
        float4 bv = *(const float4*)(bias + col0 + c4 * 4);
        d.x = (d.x + bv.x) * scale;
        d.y = (d.y + bv.y) * scale;
        d.z = (d.z + bv.z) * scale;
        d.w = (d.w + bv.w) * scale;
        size_t off = (size_t)(row0 + r) * EE + col0 + c4 * 4;
        if (mode == 0) {
            *(float4*)(Yf + off) = d;
        } else {
            uint2 h, lo;
            split4(d, h, lo);
            *(uint2*)(Yh + off) = h;
            *(uint2*)(Yl + off) = lo;
        }
    }
}

// ===========================================================================
// Tensor-core flash attention on pre-split bf16 inputs.
// Grid (T/128, B*H), 256 threads = 8 warps; warp owns 16 q-rows.
// Key chunks of 64. All loads are cp.async; V uses ldmatrix.trans.
// SMEM rows 144B (128B data + 16B pad).
// ===========================================================================
#define AROWB 144
#define A_QH 0
#define A_QL (128 * AROWB)               // 18432
#define A_KH (2 * 128 * AROWB)           // 36864
#define A_KL (A_KH + 64 * AROWB)         // 46080
#define A_VH (A_KH + 2 * 64 * AROWB)     // 55296
#define A_VL (A_VH + 64 * AROWB)         // 64512
#define ATT_SMEM_BYTES (A_VL + 64 * AROWB)   // 73728

__global__ __launch_bounds__(256, 2) void attn_tc_kernel(
    const __nv_bfloat16* __restrict__ Qh, const __nv_bfloat16* __restrict__ Ql,
    const __nv_bfloat16* __restrict__ Kh, const __nv_bfloat16* __restrict__ Kl,
    const __nv_bfloat16* __restrict__ Vh, const __nv_bfloat16* __restrict__ Vl,
    __nv_bfloat16* __restrict__ Oh, __nv_bfloat16* __restrict__ Ol)
{
    extern __shared__ char sm[];
    const uint32_t sb = smem_to_u32(sm);
    const int tid = threadIdx.x;
    const int lane = tid & 31;
    const int wid = tid >> 5;
    const int qt = blockIdx.x;
    const int bh = blockIdx.y;
    const int b = bh >> 4;
    const int h = bh & 15;
    const size_t base = ((size_t)b * TT) * EE + (size_t)h * DD;

    const int lr = lane & 15;
    const uint32_t lk = (uint32_t)(lane >> 4) << 4;
    const int quad = lane >> 2;
    const int c2 = (lane & 3) * 2;

    // async-load Q tile (128 x 64 x hi/lo), already scaled by 0.125
#pragma unroll
    for (int l = 0; l < 4; l++) {
        int f = tid + l * 256;
        int r = f >> 3, c16 = f & 7;
        size_t off = base + (size_t)(qt * 128 + r) * EE + c16 * 8;
        uint32_t d = sb + (uint32_t)r * AROWB + c16 * 16;
        cp16(d + A_QH, Qh + off);
        cp16(d + A_QL, Ql + off);
    }
    CP_COMMIT();

    float o_acc[8][4];
#pragma unroll
    for (int n8 = 0; n8 < 8; n8++)
#pragma unroll
        for (int q = 0; q < 4; q++) o_acc[n8][q] = 0.0f;
    float m0 = -1e30f, m1 = -1e30f, l0 = 0.0f, l1 = 0.0f;

    for (int kt = 0; kt < 16; kt++) {
        // async-load K and V chunks (64 x 64 x hi/lo each)
#pragma unroll
        for (int l = 0; l < 2; l++) {
            int f = tid + l * 256;
            int r = f >> 3, c16 = f & 7;
            size_t off = base + (size_t)(kt * 64 + r) * EE + c16 * 8;
            uint32_t d = sb + (uint32_t)r * AROWB + c16 * 16;
            cp16(d + A_KH, Kh + off);
            cp16(d + A_KL, Kl + off);
            cp16(d + A_VH, Vh + off);
            cp16(d + A_VL, Vl + off);
        }
        CP_COMMIT();
        CP_WAIT(0);
        __syncthreads();

        // ---- S = (Q*scale) K^T ----
        float s[8][4];
#pragma unroll
        for (int n8 = 0; n8 < 8; n8++)
#pragma unroll
            for (int q = 0; q < 4; q++) s[n8][q] = 0.0f;

#pragma unroll
        for (int kk = 0; kk < 4; kk++) {
            uint32_t kb = (uint32_t)kk * 32 + lk;
            uint32_t qh[4], ql[4];
            {
                uint32_t addr = sb + (uint32_t)(wid * 16 + lr) * AROWB + kb;
                ldsm4(qh, addr + A_QH);
                ldsm4(ql, addr + A_QL);
            }
            uint32_t kh[4][4], klo[4][4];
#pragma unroll
            for (int nt = 0; nt < 4; nt++) {
                uint32_t addr = sb + (uint32_t)(nt * 16 + lr) * AROWB + kb;
                ldsm4(kh[nt], addr + A_KH);
                ldsm4(klo[nt], addr + A_KL);
            }
#pragma unroll
            for (int n8 = 0; n8 < 8; n8++) {
                int g = n8 >> 1, o = n8 & 1;
                uint32_t b0 = kh[g][o], b1 = kh[g][o + 2];
                uint32_t c0 = klo[g][o], c1 = klo[g][o + 2];
                mma16816(s[n8], qh, b0, b1);
                mma16816(s[n8], qh, c0, c1);
                mma16816(s[n8], ql, b0, b1);
            }
        }

        // ---- online softmax on register fragments ----
        float rmax0 = -1e30f, rmax1 = -1e30f;
#pragma unroll
        for (int n8 = 0; n8 < 8; n8++) {
            rmax0 = fmaxf(rmax0, fmaxf(s[n8][0], s[n8][1]));
            rmax1 = fmaxf(rmax1, fmaxf(s[n8][2], s[n8][3]));
        }
#pragma unroll
        for (int mask = 1; mask <= 2; mask <<= 1) {
            rmax0 = fmaxf(rmax0, __shfl_xor_sync(0xffffffffu, rmax0, mask));
            rmax1 = fmaxf(rmax1, __shfl_xor_sync(0xffffffffu, rmax1, mask));
        }
        float mn0 = fmaxf(m0, rmax0), mn1 = fmaxf(m1, rmax1);
        float a0 = __expf(m0 - mn0), a1 = __expf(m1 - mn1);
        float sum0 = 0.0f, sum1 = 0.0f;
#pragma unroll
        for (int n8 = 0; n8 < 8; n8++) {
            s[n8][0] = __expf(s[n8][0] - mn0);
            s[n8][1] = __expf(s[n8][1] - mn0);
            s[n8][2] = __expf(s[n8][2] - mn1);
            s[n8][3] = __expf(s[n8][3] - mn1);
            sum0 += s[n8][0] + s[n8][1];
            sum1 += s[n8][2] + s[n8][3];
        }
#pragma unroll
        for (int mask = 1; mask <= 2; mask <<= 1) {
            sum0 += __shfl_xor_sync(0xffffffffu, sum0, mask);
            sum1 += __shfl_xor_sync(0xffffffffu, sum1, mask);
        }
        l0 = l0 * a0 + sum0; m0 = mn0;
        l1 = l1 * a1 + sum1; m1 = mn1;
#pragma unroll
        for (int n8 = 0; n8 < 8; n8++) {
            o_acc[n8][0] *= a0; o_acc[n8][1] *= a0;
            o_acc[n8][2] *= a1; o_acc[n8][3] *= a1;
        }

        // ---- O += P V : P from registers; V natural [key][d] via ldsm.trans ----
#pragma unroll
        for (int k = 0; k < 4; k++) {
            uint32_t ph[4], pl[4];
            pack_p(s[2 * k][0],     s[2 * k][1],     ph[0], pl[0]);
            pack_p(s[2 * k][2],     s[2 * k][3],     ph[1], pl[1]);
            pack_p(s[2 * k + 1][0], s[2 * k + 1][1], ph[2], pl[2]);
            pack_p(s[2 * k + 1][2], s[2 * k + 1][3], ph[3], pl[3]);

            uint32_t vrow = (uint32_t)(16 * k + ((lane >> 4) & 1) * 8 + (lane & 7));
            uint32_t vcolh = (uint32_t)((lane >> 3) & 1) * 16;
            uint32_t vh[4][4], vl[4][4];
#pragma unroll
            for (int nt = 0; nt < 4; nt++) {
                uint32_t addr = sb + vrow * AROWB + nt * 32 + vcolh;
                ldsm4t(vh[nt], addr + A_VH);
                ldsm4t(vl[nt], addr + A_VL);
            }
#pragma unroll
            for (int n8 = 0; n8 < 8; n8++) {
                int g = n8 >> 1, o = n8 & 1;
                uint32_t b0 = vh[g][o], b1 = vh[g][o + 2];
                uint32_t c0 = vl[g][o], c1 = vl[g][o + 2];
                mma16816(o_acc[n8], ph, b0, b1);
                mma16816(o_acc[n8], ph, c0, c1);
                mma16816(o_acc[n8], pl, b0, b1);
            }
        }
        __syncthreads();   // readers done before next chunk's cp.async overwrite
    }

    // ---- epilogue: normalize and store hi/lo bf16 ----
    float inv0 = 1.0f / l0, inv1 = 1.0f / l1;
    size_t r0g = base + (size_t)(qt * 128 + wid * 16 + quad) * EE;
    size_t r1g = r0g + (size_t)8 * EE;
#pragma unroll
    for (int n8 = 0; n8 < 8; n8++) {
        int col = n8 * 8 + c2;
        uint32_t h, lo;
        pack_p(o_acc[n8][0] * inv0, o_acc[n8][1] * inv0, h, lo);
        *(uint32_t*)(Oh + r0g + col) = h;
        *(uint32_t*)(Ol + r0g + col) = lo;
        pack_p(o_acc[n8][2] * inv1, o_acc[n8][3] * inv1, h, lo);
        *(uint32_t*)(Oh + r1g + col) = h;
        *(uint32_t*)(Ol + r1g + col) = lo;
    }
}

// ---------------------------------------------------------------------------
// Launch
// Inputs (metadata order): query, key, value, Wq, bq, Wk, bk, Wv, bv, Wo, bo
// ---------------------------------------------------------------------------
extern "C" void kernel_launch(void* const* d_in, const int* in_sizes, int n_in,
                              void* d_out, int out_size)
{
    const float* query = (const float*)d_in[0];
    const float* key   = (const float*)d_in[1];
    const float* value = (const float*)d_in[2];
    const float* Wq    = (const float*)d_in[3];
    const float* bq    = (const float*)d_in[4];
    const float* Wk    = (const float*)d_in[5];
    const float* bk    = (const float*)d_in[6];
    const float* Wv    = (const float*)d_in[7];
    const float* bv    = (const float*)d_in[8];
    const float* Wo    = (const float*)d_in[9];
    const float* bo    = (const float*)d_in[10];
    float* out = (float*)d_out;

    __nv_bfloat16 *Qh, *Ql, *Kh, *Kl, *Vh, *Vl, *Oh, *Ol, *Xh, *Xl, *Wh, *Wl;
    cudaGetSymbolAddress((void**)&Qh, g_Qh);
    cudaGetSymbolAddress((void**)&Ql, g_Ql);
    cudaGetSymbolAddress((void**)&Kh, g_Kh);
    cudaGetSymbolAddress((void**)&Kl, g_Kl);
    cudaGetSymbolAddress((void**)&Vh, g_Vh);
    cudaGetSymbolAddress((void**)&Vl, g_Vl);
    cudaGetSymbolAddress((void**)&Oh, g_Oh);
    cudaGetSymbolAddress((void**)&Ol, g_Ol);
    cudaGetSymbolAddress((void**)&Xh, g_Xh);
    cudaGetSymbolAddress((void**)&Xl, g_Xl);
    cudaGetSymbolAddress((void**)&Wh, g_Wh);
    cudaGetSymbolAddress((void**)&Wl, g_Wl);

    cudaFuncSetAttribute(gemm_bf_kernel,
                         cudaFuncAttributeMaxDynamicSharedMemorySize,
                         GEMM_SMEM_BYTES);
    cudaFuncSetAttribute(attn_tc_kernel,
                         cudaFuncAttributeMaxDynamicSharedMemorySize,
                         ATT_SMEM_BYTES);

    const int nx4 = NELEM / 4;            // 2097152
    const int nw4 = EE * EE / 4;          // 262144
    const int gx = (nx4 + 255) / 256;
    const int gw = (nw4 + 255) / 256;
    dim3 ggrid(EE / 128, MROWS / 128);    // (8, 64)

    // Q projection (fold attention scale 1/sqrt(64) = 0.125 into epilogue)
    split_kernel<<<gx, 256>>>((const float4*)query, (uint2*)Xh, (uint2*)Xl, nx4);
    split_kernel<<<gw, 256>>>((const float4*)Wq, (uint2*)Wh, (uint2*)Wl, nw4);
    gemm_bf_kernel<<<ggrid, 256, GEMM_SMEM_BYTES>>>(Xh, Xl, Wh, Wl, bq,
                                                    0.125f, 1, nullptr, Qh, Ql);
    // K projection
    split_kernel<<<gx, 256>>>((const float4*)key, (uint2*)Xh, (uint2*)Xl, nx4);
    split_kernel<<<gw, 256>>>((const float4*)Wk, (uint2*)Wh, (uint2*)Wl, nw4);
    gemm_bf_kernel<<<ggrid, 256, GEMM_SMEM_BYTES>>>(Xh, Xl, Wh, Wl, bk,
                                                    1.0f, 1, nullptr, Kh, Kl);
    // V projection
    split_kernel<<<gx, 256>>>((const float4*)value, (uint2*)Xh, (uint2*)Xl, nx4);
    split_kernel<<<gw, 256>>>((const float4*)Wv, (uint2*)Wh, (uint2*)Wl, nw4);
    gemm_bf_kernel<<<ggrid, 256, GEMM_SMEM_BYTES>>>(Xh, Xl, Wh, Wl, bv,
                                                    1.0f, 1, nullptr, Vh, Vl);
    // Attention
    attn_tc_kernel<<<dim3(TT / 128, BB * HH), 256, ATT_SMEM_BYTES>>>(
        Qh, Ql, Kh, Kl, Vh, Vl, Oh, Ol);
    // Output projection (fp32 final output)
    split_kernel<<<gw, 256>>>((const float4*)Wo, (uint2*)Wh, (uint2*)Wl, nw4);
    gemm_bf_kernel<<<ggrid, 256, GEMM_SMEM_BYTES>>>(Oh, Ol, Wh, Wl, bo,
                                                    1.0f, 0, out, nullptr, nullptr);
}

// round 8
// speedup vs baseline: 3.0245x; 1.0698x over previous
#include <cuda_runtime.h>
#include <cuda_bf16.h>
#include <cstdint>

// Problem constants
#define BB 8
#define TT 1024
#define EE 1024
#define HH 16
#define DD 64
#define MROWS (BB * TT)   // 8192
#define NELEM (MROWS * EE)
#define WN (EE * EE)

// Scratch (allocation-free rule: __device__ globals) — all bf16 hi/lo pairs
__device__ __nv_bfloat16 g_Xh[3 * NELEM], g_Xl[3 * NELEM];     // split inputs q/k/v
__device__ __nv_bfloat16 g_Wh[4 * WN], g_Wl[4 * WN];           // split Wq/Wk/Wv/Wo
__device__ __nv_bfloat16 g_QKVh[3 * NELEM], g_QKVl[3 * NELEM]; // projected Q/K/V
__device__ __nv_bfloat16 g_Oh[NELEM], g_Ol[NELEM];             // attention output

// ===========================================================================
// Helpers (target-agnostic PTX: ldmatrix / mma.sync / cp.async, sm_80+)
// ===========================================================================
__device__ __forceinline__ uint32_t smem_to_u32(const void* smem_ptr) {
    uint32_t addr;
    asm("{ .reg .u64 tmp; cvta.to.shared.u64 tmp, %1; cvt.u32.u64 %0, tmp; }"
        : "=r"(addr) : "l"(smem_ptr));
    return addr;
}

__device__ __forceinline__ void ldsm4(uint32_t* r, uint32_t addr) {
    asm volatile("ldmatrix.sync.aligned.m8n8.x4.shared.b16 {%0,%1,%2,%3}, [%4];"
                 : "=r"(r[0]), "=r"(r[1]), "=r"(r[2]), "=r"(r[3])
                 : "r"(addr));
}

__device__ __forceinline__ void ldsm4t(uint32_t* r, uint32_t addr) {
    asm volatile("ldmatrix.sync.aligned.m8n8.x4.trans.shared.b16 {%0,%1,%2,%3}, [%4];"
                 : "=r"(r[0]), "=r"(r[1]), "=r"(r[2]), "=r"(r[3])
                 : "r"(addr));
}

__device__ __forceinline__ void mma16816(float* c, const uint32_t* a,
                                         uint32_t b0, uint32_t b1) {
    asm volatile(
        "mma.sync.aligned.m16n8k16.row.col.f32.bf16.bf16.f32 "
        "{%0,%1,%2,%3}, {%4,%5,%6,%7}, {%8,%9}, {%0,%1,%2,%3};"
        : "+f"(c[0]), "+f"(c[1]), "+f"(c[2]), "+f"(c[3])
        : "r"(a[0]), "r"(a[1]), "r"(a[2]), "r"(a[3]), "r"(b0), "r"(b1));
}

__device__ __forceinline__ void cp16(uint32_t dst, const void* src) {
    asm volatile("cp.async.cg.shared.global [%0], [%1], 16;"
                 :: "r"(dst), "l"(src));
}
#define CP_COMMIT() asm volatile("cp.async.commit_group;" ::: "memory")
#define CP_WAIT(n)  asm volatile("cp.async.wait_group %0;" :: "n"(n) : "memory")

// Split fp32 pair -> hi bf16x2 (truncated) + lo bf16x2 (rn residual).
__device__ __forceinline__ void pack_p(float x0, float x1, uint32_t& hi,
                                       uint32_t& lo) {
    uint32_t u0 = __float_as_uint(x0), u1 = __float_as_uint(x1);
    hi = __byte_perm(u0, u1, 0x7632);
    float l0 = x0 - __uint_as_float(u0 & 0xFFFF0000u);
    float l1 = x1 - __uint_as_float(u1 & 0xFFFF0000u);
    asm("cvt.rn.bf16x2.f32 %0, %1, %2;" : "=r"(lo) : "f"(l1), "f"(l0));
}

__device__ __forceinline__ void split4(float4 v, uint2& hi, uint2& lo) {
    uint32_t h0, l0, h1, l1;
    pack_p(v.x, v.y, h0, l0);
    pack_p(v.z, v.w, h1, l1);
    hi = make_uint2(h0, h1);
    lo = make_uint2(l0, l1);
}

// ===========================================================================
// Prepass splits (batched over grid.z)
// ===========================================================================
__global__ __launch_bounds__(256) void split_x_kernel(
    const float4* __restrict__ x0, const float4* __restrict__ x1,
    const float4* __restrict__ x2)
{
    const int z = blockIdx.z;
    const float4* x = (z == 0) ? x0 : (z == 1) ? x1 : x2;
    size_t i = (size_t)blockIdx.x * 256 + threadIdx.x;   // grid.x = NELEM/4/256
    uint2 h, l;
    split4(x[i], h, l);
    ((uint2*)g_Xh)[(size_t)z * (NELEM / 4) + i] = h;
    ((uint2*)g_Xl)[(size_t)z * (NELEM / 4) + i] = l;
}

__global__ __launch_bounds__(256) void split_w_kernel(
    const float4* __restrict__ w0, const float4* __restrict__ w1,
    const float4* __restrict__ w2, const float4* __restrict__ w3)
{
    const int z = blockIdx.z;
    const float4* w = (z == 0) ? w0 : (z == 1) ? w1 : (z == 2) ? w2 : w3;
    size_t i = (size_t)blockIdx.x * 256 + threadIdx.x;   // grid.x = WN/4/256
    uint2 h, l;
    split4(w[i], h, l);
    ((uint2*)g_Wh)[(size_t)z * (WN / 4) + i] = h;
    ((uint2*)g_Wl)[(size_t)z * (WN / 4) + i] = l;
}

// ===========================================================================
// HMMA GEMM body on pre-split bf16: Y[M,N] = X @ W^T + bias (M=8192, N=K=1024)
// Tile 128x128, BK=32, 256 threads = 8 warps (4x2), warp tile 32x64.
// 2-stage cp.async pipeline. SMEM rows 80B (64B data + 16B pad).
// mode 0: write fp32 Y. mode 1: write hi/lo bf16 (scaled).
// ===========================================================================
#define ROWB 80
#define MATB (128 * ROWB)             // 10240 B per matrix buffer
#define STAGEB (4 * MATB)             // Ah, Al, Bh, Bl = 40960 B
#define GEMM_SMEM_BYTES (2 * STAGEB)  // 81920 B

__device__ __forceinline__ uint32_t ds_swz(int r, uint32_t cbytes) {
    return (uint32_t)r * 512u + (cbytes ^ (((uint32_t)r & 7u) << 4));
}

__device__ __forceinline__ void gemm_body(
    const __nv_bfloat16* __restrict__ Ah, const __nv_bfloat16* __restrict__ Al,
    const __nv_bfloat16* __restrict__ Bh, const __nv_bfloat16* __restrict__ Bl,
    const float* __restrict__ bias, float scale, int mode,
    float* __restrict__ Yf, __nv_bfloat16* __restrict__ Yh,
    __nv_bfloat16* __restrict__ Yl, char* smem)
{
    const uint32_t sb = smem_to_u32(smem);
    const int tid = threadIdx.x;
    const int lane = tid & 31;
    const int wid = tid >> 5;
    const int wm = wid & 3;
    const int wn = wid >> 2;
    const int row0 = blockIdx.y * 128;
    const int col0 = blockIdx.x * 128;

    float acc[2][8][4];
#pragma unroll
    for (int mt = 0; mt < 2; mt++)
#pragma unroll
        for (int n8 = 0; n8 < 8; n8++)
#pragma unroll
            for (int q = 0; q < 4; q++) acc[mt][n8][q] = 0.0f;

    // prologue: async-load chunk 0 into stage 0
    {
        uint32_t S = sb;
#pragma unroll
        for (int l = 0; l < 2; l++) {
            int f = tid + l * 256;
            int r = f >> 2, c16 = f & 3;
            uint32_t d = S + (uint32_t)r * ROWB + c16 * 16;
            size_t offA = (size_t)(row0 + r) * EE + c16 * 8;
            size_t offB = (size_t)(col0 + r) * EE + c16 * 8;
            cp16(d, Ah + offA);
            cp16(d + MATB, Al + offA);
            cp16(d + 2 * MATB, Bh + offB);
            cp16(d + 3 * MATB, Bl + offB);
        }
        CP_COMMIT();
    }

    const int lr = lane & 15;
    const uint32_t lk = (uint32_t)(lane >> 4) << 4;

    for (int c = 0; c < 32; c++) {
        if (c < 31) {
            uint32_t S = sb + (uint32_t)((c + 1) & 1) * STAGEB;
#pragma unroll
            for (int l = 0; l < 2; l++) {
                int f = tid + l * 256;
                int r = f >> 2, c16 = f & 3;
                uint32_t d = S + (uint32_t)r * ROWB + c16 * 16;
                size_t offA = (size_t)(row0 + r) * EE + (c + 1) * 32 + c16 * 8;
                size_t offB = (size_t)(col0 + r) * EE + (c + 1) * 32 + c16 * 8;
                cp16(d, Ah + offA);
                cp16(d + MATB, Al + offA);
                cp16(d + 2 * MATB, Bh + offB);
                cp16(d + 3 * MATB, Bl + offB);
            }
            CP_COMMIT();
            CP_WAIT(1);
        } else {
            CP_WAIT(0);
        }
        __syncthreads();

        {
            uint32_t SA = sb + (uint32_t)(c & 1) * STAGEB;
            uint32_t SB = SA + 2 * MATB;
#pragma unroll
            for (int kk = 0; kk < 2; kk++) {
                uint32_t kb = (uint32_t)kk * 32 + lk;
                uint32_t ah[2][4], al[2][4];
#pragma unroll
                for (int mt = 0; mt < 2; mt++) {
                    uint32_t addr = SA + (uint32_t)(wm * 32 + mt * 16 + lr) * ROWB + kb;
                    ldsm4(ah[mt], addr);
                    ldsm4(al[mt], addr + MATB);
                }
                uint32_t bh[4][4], bl[4][4];
#pragma unroll
                for (int nt = 0; nt < 4; nt++) {
                    uint32_t addr = SB + (uint32_t)(wn * 64 + nt * 16 + lr) * ROWB + kb;
                    ldsm4(bh[nt], addr);
                    ldsm4(bl[nt], addr + MATB);
                }
#pragma unroll
                for (int mt = 0; mt < 2; mt++) {
#pragma unroll
                    for (int n8 = 0; n8 < 8; n8++) {
                        int g = n8 >> 1, o = n8 & 1;
                        uint32_t b0 = bh[g][o], b1 = bh[g][o + 2];
                        uint32_t c0 = bl[g][o], c1 = bl[g][o + 2];
                        mma16816(acc[mt][n8], ah[mt], b0, b1);
                        mma16816(acc[mt][n8], ah[mt], c0, c1);
                        mma16816(acc[mt][n8], al[mt], b0, b1);
                    }
                }
            }
        }
        __syncthreads();
    }

    // epilogue: stage fp32 in swizzled smem, then coalesced output
    char* Ds = smem;
#pragma unroll
    for (int mt = 0; mt < 2; mt++) {
#pragma unroll
        for (int n8 = 0; n8 < 8; n8++) {
            int r = wm * 32 + mt * 16 + (lane >> 2);
            uint32_t cb = (uint32_t)(wn * 64 + n8 * 8 + (lane & 3) * 2) * 4u;
            *(float2*)(Ds + ds_swz(r, cb)) =
                make_float2(acc[mt][n8][0], acc[mt][n8][1]);
            *(float2*)(Ds + ds_swz(r + 8, cb)) =
                make_float2(acc[mt][n8][2], acc[mt][n8][3]);
        }
    }
    __syncthreads();

#pragma unroll
    for (int l = 0; l < 16; l++) {
        int f = tid + l * 256;
        int r = f >> 5;
        int c4 = f & 31;
        float4 d = *(float4*)(Ds + ds_swz(r, (uint32_t)c4 * 16u));
        float4 bv = *(const float4*)(bias + col0 + c4 * 4);
        d.x = (d.x + bv.x) * scale;
        d.y = (d.y + bv.y) * scale;
        d.z = (d.z + bv.z) * scale;
        d.w = (d.w + bv.w) * scale;
        size_t off = (size_t)(row0 + r) * EE + col0 + c4 * 4;
        if (mode == 0) {
            *(float4*)(Yf + off) = d;
        } else {
            uint2 h, lo;
            split4(d, h, lo);
            *(uint2*)(Yh + off) = h;
            *(uint2*)(Yl + off) = lo;
        }
    }
}

// Batched QKV projection: grid (8, 64, 3); z selects input/weight/bias/output.
__global__ __launch_bounds__(256, 2) void gemm_qkv_kernel(
    const float* __restrict__ bq, const float* __restrict__ bk,
    const float* __restrict__ bv)
{
    extern __shared__ char smem[];
    const int z = blockIdx.z;
    const float* bias = (z == 0) ? bq : (z == 1) ? bk : bv;
    const float scale = (z == 0) ? 0.125f : 1.0f;   // fold 1/sqrt(D) into Q
    gemm_body(g_Xh + (size_t)z * NELEM, g_Xl + (size_t)z * NELEM,
              g_Wh + (size_t)z * WN, g_Wl + (size_t)z * WN,
              bias, scale, 1, nullptr,
              g_QKVh + (size_t)z * NELEM, g_QKVl + (size_t)z * NELEM, smem);
}

// Output projection: fp32 result to harness buffer.
__global__ __launch_bounds__(256, 2) void gemm_o_kernel(
    const float* __restrict__ bo, float* __restrict__ out)
{
    extern __shared__ char smem[];
    gemm_body(g_Oh, g_Ol, g_Wh + (size_t)3 * WN, g_Wl + (size_t)3 * WN,
              bo, 1.0f, 0, out, nullptr, nullptr, smem);
}

// ===========================================================================
// Tensor-core flash attention, pre-split bf16, 2-stage K/V cp.async pipeline.
// Grid (T/128, B*H), 256 threads = 8 warps; warp owns 16 q-rows; key chunks 64.
// SMEM rows 144B (128B data + 16B pad).
//   Q  (hi/lo): [0, 36864)
//   KV stages:  [36864 + st*36864): KH, KL, VH, VL (9216 B each)
// ===========================================================================
#define AROWB 144
#define A_QH 0
#define A_QL 18432
#define A_KV 36864
#define KVST 36864
#define S_KH 0
#define S_KL 9216
#define S_VH 18432
#define S_VL 27648
#define ATT_SMEM_BYTES (A_KV + 2 * KVST)   // 110592

__global__ __launch_bounds__(256, 2) void attn_tc_kernel()
{
    extern __shared__ char sm[];
    const uint32_t sb = smem_to_u32(sm);
    const int tid = threadIdx.x;
    const int lane = tid & 31;
    const int wid = tid >> 5;
    const int qt = blockIdx.x;
    const int bh = blockIdx.y;
    const int b = bh >> 4;
    const int h = bh & 15;
    const size_t base = ((size_t)b * TT) * EE + (size_t)h * DD;

    const __nv_bfloat16* Qh = g_QKVh;
    const __nv_bfloat16* Ql = g_QKVl;
    const __nv_bfloat16* Kh = g_QKVh + NELEM;
    const __nv_bfloat16* Kl = g_QKVl + NELEM;
    const __nv_bfloat16* Vh = g_QKVh + 2 * NELEM;
    const __nv_bfloat16* Vl = g_QKVl + 2 * NELEM;

    const int lr = lane & 15;
    const uint32_t lk = (uint32_t)(lane >> 4) << 4;
    const int quad = lane >> 2;
    const int c2 = (lane & 3) * 2;

    // prologue: Q tile (group 0), K/V chunk 0 (group 1)
#pragma unroll
    for (int l = 0; l < 4; l++) {
        int f = tid + l * 256;
        int r = f >> 3, c16 = f & 7;
        size_t off = base + (size_t)(qt * 128 + r) * EE + c16 * 8;
        uint32_t d = sb + (uint32_t)r * AROWB + c16 * 16;
        cp16(d + A_QH, Qh + off);
        cp16(d + A_QL, Ql + off);
    }
    CP_COMMIT();
    {
#pragma unroll
        for (int l = 0; l < 2; l++) {
            int f = tid + l * 256;
            int r = f >> 3, c16 = f & 7;
            size_t off = base + (size_t)r * EE + c16 * 8;
            uint32_t d = sb + A_KV + (uint32_t)r * AROWB + c16 * 16;
            cp16(d + S_KH, Kh + off);
            cp16(d + S_KL, Kl + off);
            cp16(d + S_VH, Vh + off);
            cp16(d + S_VL, Vl + off);
        }
        CP_COMMIT();
    }

    float o_acc[8][4];
#pragma unroll
    for (int n8 = 0; n8 < 8; n8++)
#pragma unroll
        for (int q = 0; q < 4; q++) o_acc[n8][q] = 0.0f;
    float m0 = -1e30f, m1 = -1e30f, l0 = 0.0f, l1 = 0.0f;

    for (int kt = 0; kt < 16; kt++) {
        // issue next chunk into alternate stage, then wait for current stage
        if (kt < 15) {
            uint32_t S = sb + A_KV + (uint32_t)((kt + 1) & 1) * KVST;
#pragma unroll
            for (int l = 0; l < 2; l++) {
                int f = tid + l * 256;
                int r = f >> 3, c16 = f & 7;
                size_t off = base + (size_t)((kt + 1) * 64 + r) * EE + c16 * 8;
                uint32_t d = S + (uint32_t)r * AROWB + c16 * 16;
                cp16(d + S_KH, Kh + off);
                cp16(d + S_KL, Kl + off);
                cp16(d + S_VH, Vh + off);
                cp16(d + S_VL, Vl + off);
            }
            CP_COMMIT();
            CP_WAIT(1);
        } else {
            CP_WAIT(0);
        }
        __syncthreads();

        const uint32_t kvb = sb + A_KV + (uint32_t)(kt & 1) * KVST;

        // ---- S = (Q*scale) K^T ----
        float s[8][4];
#pragma unroll
        for (int n8 = 0; n8 < 8; n8++)
#pragma unroll
            for (int q = 0; q < 4; q++) s[n8][q] = 0.0f;

#pragma unroll
        for (int kk = 0; kk < 4; kk++) {
            uint32_t kb = (uint32_t)kk * 32 + lk;
            uint32_t qh[4], ql[4];
            {
                uint32_t addr = sb + (uint32_t)(wid * 16 + lr) * AROWB + kb;
                ldsm4(qh, addr + A_QH);
                ldsm4(ql, addr + A_QL);
            }
            uint32_t kh[4][4], klo[4][4];
#pragma unroll
            for (int nt = 0; nt < 4; nt++) {
                uint32_t addr = kvb + (uint32_t)(nt * 16 + lr) * AROWB + kb;
                ldsm4(kh[nt], addr + S_KH);
                ldsm4(klo[nt], addr + S_KL);
            }
#pragma unroll
            for (int n8 = 0; n8 < 8; n8++) {
                int g = n8 >> 1, o = n8 & 1;
                uint32_t b0 = kh[g][o], b1 = kh[g][o + 2];
                uint32_t c0 = klo[g][o], c1 = klo[g][o + 2];
                mma16816(s[n8], qh, b0, b1);
                mma16816(s[n8], qh, c0, c1);
                mma16816(s[n8], ql, b0, b1);
            }
        }

        // ---- online softmax on register fragments ----
        float rmax0 = -1e30f, rmax1 = -1e30f;
#pragma unroll
        for (int n8 = 0; n8 < 8; n8++) {
            rmax0 = fmaxf(rmax0, fmaxf(s[n8][0], s[n8][1]));
            rmax1 = fmaxf(rmax1, fmaxf(s[n8][2], s[n8][3]));
        }
#pragma unroll
        for (int mask = 1; mask <= 2; mask <<= 1) {
            rmax0 = fmaxf(rmax0, __shfl_xor_sync(0xffffffffu, rmax0, mask));
            rmax1 = fmaxf(rmax1, __shfl_xor_sync(0xffffffffu, rmax1, mask));
        }
        float mn0 = fmaxf(m0, rmax0), mn1 = fmaxf(m1, rmax1);
        float a0 = __expf(m0 - mn0), a1 = __expf(m1 - mn1);
        float sum0 = 0.0f, sum1 = 0.0f;
#pragma unroll
        for (int n8 = 0; n8 < 8; n8++) {
            s[n8][0] = __expf(s[n8][0] - mn0);
            s[n8][1] = __expf(s[n8][1] - mn0);
            s[n8][2] = __expf(s[n8][2] - mn1);
            s[n8][3] = __expf(s[n8][3] - mn1);
            sum0 += s[n8][0] + s[n8][1];
            sum1 += s[n8][2] + s[n8][3];
        }
#pragma unroll
        for (int mask = 1; mask <= 2; mask <<= 1) {
            sum0 += __shfl_xor_sync(0xffffffffu, sum0, mask);
            sum1 += __shfl_xor_sync(0xffffffffu, sum1, mask);
        }
        l0 = l0 * a0 + sum0; m0 = mn0;
        l1 = l1 * a1 + sum1; m1 = mn1;
#pragma unroll
        for (int n8 = 0; n8 < 8; n8++) {
            o_acc[n8][0] *= a0; o_acc[n8][1] *= a0;
            o_acc[n8][2] *= a1; o_acc[n8][3] *= a1;
        }

        // ---- O += P V : P from registers; V natural [key][d] via ldsm.trans ----
#pragma unroll
        for (int k = 0; k < 4; k++) {
            uint32_t ph[4], pl[4];
            pack_p(s[2 * k][0],     s[2 * k][1],     ph[0], pl[0]);
            pack_p(s[2 * k][2],     s[2 * k][3],     ph[1], pl[1]);
            pack_p(s[2 * k + 1][0], s[2 * k + 1][1], ph[2], pl[2]);
            pack_p(s[2 * k + 1][2], s[2 * k + 1][3], ph[3], pl[3]);

            uint32_t vrow = (uint32_t)(16 * k + ((lane >> 4) & 1) * 8 + (lane & 7));
            uint32_t vcolh = (uint32_t)((lane >> 3) & 1) * 16;
            uint32_t vh[4][4], vl[4][4];
#pragma unroll
            for (int nt = 0; nt < 4; nt++) {
                uint32_t addr = kvb + vrow * AROWB + nt * 32 + vcolh;
                ldsm4t(vh[nt], addr + S_VH);
                ldsm4t(vl[nt], addr + S_VL);
            }
#pragma unroll
            for (int n8 = 0; n8 < 8; n8++) {
                int g = n8 >> 1, o = n8 & 1;
                uint32_t b0 = vh[g][o], b1 = vh[g][o + 2];
                uint32_t c0 = vl[g][o], c1 = vl[g][o + 2];
                mma16816(o_acc[n8], ph, b0, b1);
                mma16816(o_acc[n8], ph, c0, c1);
                mma16816(o_acc[n8], pl, b0, b1);
            }
        }
        __syncthreads();   // readers done before this stage is overwritten
    }

    // ---- epilogue: normalize and store hi/lo bf16 ----
    float inv0 = 1.0f / l0, inv1 = 1.0f / l1;
    size_t r0g = base + (size_t)(qt * 128 + wid * 16 + quad) * EE;
    size_t r1g = r0g + (size_t)8 * EE;
#pragma unroll
    for (int n8 = 0; n8 < 8; n8++) {
        int col = n8 * 8 + c2;
        uint32_t h2, lo2;
        pack_p(o_acc[n8][0] * inv0, o_acc[n8][1] * inv0, h2, lo2);
        *(uint32_t*)(g_Oh + r0g + col) = h2;
        *(uint32_t*)(g_Ol + r0g + col) = lo2;
        pack_p(o_acc[n8][2] * inv1, o_acc[n8][3] * inv1, h2, lo2);
        *(uint32_t*)(g_Oh + r1g + col) = h2;
        *(uint32_t*)(g_Ol + r1g + col) = lo2;
    }
}

// ---------------------------------------------------------------------------
// Launch
// Inputs (metadata order): query, key, value, Wq, bq, Wk, bk, Wv, bv, Wo, bo
// ---------------------------------------------------------------------------
extern "C" void kernel_launch(void* const* d_in, const int* in_sizes, int n_in,
                              void* d_out, int out_size)
{
    const float* query = (const float*)d_in[0];
    const float* key   = (const float*)d_in[1];
    const float* value = (const float*)d_in[2];
    const float* Wq    = (const float*)d_in[3];
    const float* bq    = (const float*)d_in[4];
    const float* Wk    = (const float*)d_in[5];
    const float* bk    = (const float*)d_in[6];
    const float* Wv    = (const float*)d_in[7];
    const float* bv    = (const float*)d_in[8];
    const float* Wo    = (const float*)d_in[9];
    const float* bo    = (const float*)d_in[10];
    float* out = (float*)d_out;

    cudaFuncSetAttribute(gemm_qkv_kernel,
                         cudaFuncAttributeMaxDynamicSharedMemorySize,
                         GEMM_SMEM_BYTES);
    cudaFuncSetAttribute(gemm_o_kernel,
                         cudaFuncAttributeMaxDynamicSharedMemorySize,
                         GEMM_SMEM_BYTES);
    cudaFuncSetAttribute(attn_tc_kernel,
                         cudaFuncAttributeMaxDynamicSharedMemorySize,
                         ATT_SMEM_BYTES);

    // Batched splits: weights (4) and inputs (3)
    split_w_kernel<<<dim3(WN / 4 / 256, 1, 4), 256>>>(
        (const float4*)Wq, (const float4*)Wk, (const float4*)Wv,
        (const float4*)Wo);
    split_x_kernel<<<dim3(NELEM / 4 / 256, 1, 3), 256>>>(
        (const float4*)query, (const float4*)key, (const float4*)value);

    // Batched Q/K/V projections
    gemm_qkv_kernel<<<dim3(EE / 128, MROWS / 128, 3), 256, GEMM_SMEM_BYTES>>>(
        bq, bk, bv);

    // Attention
    attn_tc_kernel<<<dim3(TT / 128, BB * HH), 256, ATT_SMEM_BYTES>>>();

    // Output projection (fp32 final output)
    gemm_o_kernel<<<dim3(EE / 128, MROWS / 128), 256, GEMM_SMEM_BYTES>>>(bo, out);
}